// round 8
// baseline (speedup 1.0000x reference)
#include <cuda_runtime.h>
#include <cuda_bf16.h>
#include <math.h>
#include <stdint.h>

// Problem constants
#define DIMN  2048
#define BATCH 16384

// GEMM tiling
#define BM    128
#define BN    128
#define BK    64
#define ROWB  144u                    // 128B data + 16B pad -> conflict-free LDSM
#define TILEB (128u * ROWB)           // 18432 B per bf16 tile
#define STAGEB (4u * TILEB)           // Ahi,Alo,Bhi,Blo = 73728 B
#define NST   3
#define SMEM_GEMM (NST * STAGEB)      // 221184 B

// ---------------------------------------------------------------------------
// Device scratch (static — no runtime allocs)
// ---------------------------------------------------------------------------
__device__ __align__(128) __nv_bfloat16 g_Dt_hi [DIMN * DIMN];
__device__ __align__(128) __nv_bfloat16 g_Dt_lo [DIMN * DIMN];
__device__ __align__(128) __nv_bfloat16 g_Dm_hi [DIMN * DIMN];
__device__ __align__(128) __nv_bfloat16 g_Dm_lo [DIMN * DIMN];
__device__ __align__(128) __nv_bfloat16 g_W1_hi [1024 * DIMN];
__device__ __align__(128) __nv_bfloat16 g_W1_lo [1024 * DIMN];
__device__ __align__(128) __nv_bfloat16 g_A1_hi [1024 * DIMN];
__device__ __align__(128) __nv_bfloat16 g_A1_lo [1024 * DIMN];
__device__ __align__(128) __nv_bfloat16 g_W1e_hi[1024 * DIMN];
__device__ __align__(128) __nv_bfloat16 g_W1e_lo[1024 * DIMN];
__device__ __align__(128) __nv_bfloat16 g_x_hi  [BATCH * DIMN];
__device__ __align__(128) __nv_bfloat16 g_x_lo  [BATCH * DIMN];
__device__ __align__(128) __nv_bfloat16 g_h1_hi [BATCH * 1024];
__device__ __align__(128) __nv_bfloat16 g_h1_lo [BATCH * 1024];
__device__ __align__(128) __nv_bfloat16 g_W2_hi [512 * 1024];
__device__ __align__(128) __nv_bfloat16 g_W2_lo [512 * 1024];
__device__ __align__(128) __nv_bfloat16 g_h2_hi [BATCH * 512];
__device__ __align__(128) __nv_bfloat16 g_h2_lo [BATCH * 512];
__device__ __align__(128) __nv_bfloat16 g_Wml_hi[512 * 512];
__device__ __align__(128) __nv_bfloat16 g_Wml_lo[512 * 512];
__device__ __align__(128) float g_part[4 * 1024 * DIMN];   // split-K partials
__device__ float g_bml[512];
__device__ float g_bscale[DIMN];

// ---------------------------------------------------------------------------
// Band-scale (verified round 1)
// ---------------------------------------------------------------------------
__global__ void build_scale_kernel(const float* __restrict__ fw,
                                   const float* __restrict__ kptr)
{
    int idx = blockIdx.x * blockDim.x + threadIdx.x;
    if (idx >= DIMN) return;
    const float kv = *kptr;
    float val = 1.0f;
    const double step = 2047.0 / 30.0;
    #pragma unroll 1
    for (int i = 0; i < 30; i++) {
        int s = (int)(step * (double)i);
        int e = (i == 29) ? 2047 : (int)(step * (double)(i + 1));
        if (idx >= s && idx < e) {
            float f;
            if (e <= 30) f = 1.0f + fw[i] * kv * (1.0f - (float)i / 30.0f);
            else         f = 1.0f - fw[i] * kv * (1.0f - (float)(i - 30) / 30.0f);
            val = f;
        }
    }
    g_bscale[idx] = val;
}

static __device__ __forceinline__ void bsplit(float v, __nv_bfloat16& h, __nv_bfloat16& l)
{
    h = __float2bfloat16_rn(v);
    l = __float2bfloat16_rn(v - __bfloat162float(h));
}

static __device__ __forceinline__ uint32_t packbf(__nv_bfloat16 a, __nv_bfloat16 b)
{
    __nv_bfloat162 t(a, b);
    return *reinterpret_cast<uint32_t*>(&t);
}

// ---------------------------------------------------------------------------
// Build Dt (D^T) and Dm (D) as bf16 hi/lo (verified round 4)
// ---------------------------------------------------------------------------
__global__ void build_D_kernel()
{
    int idx = blockIdx.x * blockDim.x + threadIdx.x;
    int r = idx >> 11;
    int c = idx & (DIMN - 1);
    const float n0 = 0.022097086912079612f;  // sqrt(1/2048)
    const float n1 = 0.03125f;               // sqrt(2/2048)

    int q1 = ((2 * r + 1) * c) & 8191;
    float v1 = cospif((float)q1 * (1.0f / 4096.0f)) * ((c == 0) ? n0 : n1);
    bsplit(v1, g_Dt_hi[idx], g_Dt_lo[idx]);

    int q2 = ((2 * c + 1) * r) & 8191;
    float v2 = cospif((float)q2 * (1.0f / 4096.0f)) * ((r == 0) ? n0 : n1);
    bsplit(v2, g_Dm_hi[idx], g_Dm_lo[idx]);
}

// ---------------------------------------------------------------------------
// fp32 -> bf16 hi/lo split, 8 elems/thread, 16B hi/lo stores (n % 8 == 0)
// ---------------------------------------------------------------------------
__global__ void convert_split(const float* __restrict__ s,
                              __nv_bfloat16* __restrict__ hi,
                              __nv_bfloat16* __restrict__ lo, int n)
{
    int i = (blockIdx.x * blockDim.x + threadIdx.x) << 3;
    if (i >= n) return;
    float4 v0 = *(const float4*)(s + i);
    float4 v1 = *(const float4*)(s + i + 4);
    __nv_bfloat16 h0, h1, h2, h3, h4, h5, h6, h7;
    __nv_bfloat16 l0, l1, l2, l3, l4, l5, l6, l7;
    bsplit(v0.x, h0, l0); bsplit(v0.y, h1, l1);
    bsplit(v0.z, h2, l2); bsplit(v0.w, h3, l3);
    bsplit(v1.x, h4, l4); bsplit(v1.y, h5, l5);
    bsplit(v1.z, h6, l6); bsplit(v1.w, h7, l7);
    uint4 hbuf, lbuf;
    hbuf.x = packbf(h0, h1); hbuf.y = packbf(h2, h3);
    hbuf.z = packbf(h4, h5); hbuf.w = packbf(h6, h7);
    lbuf.x = packbf(l0, l1); lbuf.y = packbf(l2, l3);
    lbuf.z = packbf(l4, l5); lbuf.w = packbf(l6, l7);
    *(uint4*)(hi + i) = hbuf;
    *(uint4*)(lo + i) = lbuf;
}

// sum 4 split-K fp32 partials -> (optional colscale) -> bf16 hi/lo
// N must be a power of two.
__global__ void reduce4_split(const float* __restrict__ part,
                              const float* __restrict__ colscale,
                              __nv_bfloat16* __restrict__ hi,
                              __nv_bfloat16* __restrict__ lo,
                              int n, int N)
{
    int i = (blockIdx.x * blockDim.x + threadIdx.x) << 2;
    if (i >= n) return;
    float4 a = *(const float4*)(part + i);
    float4 b = *(const float4*)(part + (size_t)n + i);
    float4 c = *(const float4*)(part + 2 * (size_t)n + i);
    float4 d = *(const float4*)(part + 3 * (size_t)n + i);
    float v0 = (a.x + b.x) + (c.x + d.x);
    float v1 = (a.y + b.y) + (c.y + d.y);
    float v2 = (a.z + b.z) + (c.z + d.z);
    float v3 = (a.w + b.w) + (c.w + d.w);
    if (colscale) {
        int col = i & (N - 1);
        v0 *= colscale[col];     v1 *= colscale[col + 1];
        v2 *= colscale[col + 2]; v3 *= colscale[col + 3];
    }
    __nv_bfloat16 h0, h1, h2, h3, l0, l1, l2, l3;
    bsplit(v0, h0, l0); bsplit(v1, h1, l1);
    bsplit(v2, h2, l2); bsplit(v3, h3, l3);
    __nv_bfloat162 hp0(h0, h1), hp1(h2, h3), lp0(l0, l1), lp1(l2, l3);
    *(__nv_bfloat162*)(hi + i)     = hp0;
    *(__nv_bfloat162*)(hi + i + 2) = hp1;
    *(__nv_bfloat162*)(lo + i)     = lp0;
    *(__nv_bfloat162*)(lo + i + 2) = lp1;
}

__global__ void merge_bias(const float* __restrict__ bmu, const float* __restrict__ blv)
{
    int i = blockIdx.x * blockDim.x + threadIdx.x;
    if (i < 256)      g_bml[i] = bmu[i];
    else if (i < 512) g_bml[i] = blv[i - 256];
}

// ---------------------------------------------------------------------------
// mma.sync / ldmatrix / cp.async helpers
// ---------------------------------------------------------------------------
#define LDSM4(r0, r1, r2, r3, addr)                                            \
    asm volatile("ldmatrix.sync.aligned.m8n8.x4.shared.b16 {%0,%1,%2,%3}, [%4];" \
                 : "=r"(r0), "=r"(r1), "=r"(r2), "=r"(r3) : "r"(addr))

#define MMA16816(c, a, b)                                                      \
    asm volatile("mma.sync.aligned.m16n8k16.row.col.f32.bf16.bf16.f32 "        \
                 "{%0,%1,%2,%3},{%4,%5,%6,%7},{%8,%9},{%0,%1,%2,%3};"          \
                 : "+f"((c)[0]), "+f"((c)[1]), "+f"((c)[2]), "+f"((c)[3])      \
                 : "r"((a)[0]), "r"((a)[1]), "r"((a)[2]), "r"((a)[3]),         \
                   "r"((b)[0]), "r"((b)[1]))

#define CP16(sa, ga)                                                           \
    asm volatile("cp.async.cg.shared.global [%0], [%1], 16;"                   \
                 :: "r"(sa), "l"(ga) : "memory")
#define CP_COMMIT() asm volatile("cp.async.commit_group;" ::: "memory")
#define CP_WAIT()   asm volatile("cp.async.wait_group %0;" :: "n"(NST - 2) : "memory")

// Fragment register block: [0..7]=Ah, [8..15]=Al, [16..31]=Bh, [32..47]=Bl
#define F_AH(F, mf) (&(F)[(mf) * 4])
#define F_AL(F, mf) (&(F)[8 + (mf) * 4])
#define F_BH(F, bf) (&(F)[16 + (bf) * 4])
#define F_BL(F, bf) (&(F)[32 + (bf) * 4])

// ---------------------------------------------------------------------------
// bf16x3 tensor-core NT GEMM, cp.async 3-stage pipeline, BK=64,
// register double-buffered fragments, TERM-MAJOR MMA issue order
// (16 independent accumulators between dependent MMAs on the same acc).
// ---------------------------------------------------------------------------
__global__ __launch_bounds__(256, 1)
void gemm_bf16x3(const __nv_bfloat16* __restrict__ Ahp,
                 const __nv_bfloat16* __restrict__ Alp,
                 const __nv_bfloat16* __restrict__ Bhp,
                 const __nv_bfloat16* __restrict__ Blp,
                 const float* __restrict__ bias,
                 const float* __restrict__ colscale,
                 __nv_bfloat16* __restrict__ Ch,
                 __nv_bfloat16* __restrict__ Cl,
                 float* __restrict__ Cf,
                 float* __restrict__ Cpart,
                 int M, int N, int K, int klen, int do_relu)
{
    extern __shared__ __align__(1024) char smem[];
    const uint32_t sb = (uint32_t)__cvta_generic_to_shared(smem);

    const int tid   = threadIdx.x;
    const int lane  = tid & 31;
    const int wid   = tid >> 5;
    const int warpm = wid & 3;
    const int warpn = wid >> 2;
    const int bm = blockIdx.y * BM;
    const int bn = blockIdx.x * BN;
    const int kbase = blockIdx.z * klen;

    const uint32_t aOff = (uint32_t)(warpm * 32 + (lane & 15)) * ROWB
                        + (uint32_t)(lane >> 4) * 16u;
    const uint32_t bOff = (uint32_t)(warpn * 64 + (lane & 7) + ((lane & 16) ? 8 : 0)) * ROWB
                        + (uint32_t)((lane >> 3) & 1) * 16u;

    float acc[2][8][4];
    #pragma unroll
    for (int i = 0; i < 2; i++)
        #pragma unroll
        for (int j = 0; j < 8; j++)
            #pragma unroll
            for (int q = 0; q < 4; q++) acc[i][j][q] = 0.0f;

    const int nk = klen >> 6;

    auto issue_stage = [&](int kt) {
        const uint32_t base = sb + (uint32_t)(kt % NST) * STAGEB;
        const size_t kof = (size_t)kbase + (size_t)kt * BK;
        #pragma unroll
        for (int h = 0; h < 4; h++) {
            const int c   = tid + h * 256;
            const int row = c >> 3;
            const int q   = c & 7;
            const uint32_t so = (uint32_t)row * ROWB + (uint32_t)q * 16u;
            const size_t ga = (size_t)(bm + row) * K + kof + (size_t)q * 8;
            const size_t gb = (size_t)(bn + row) * K + kof + (size_t)q * 8;
            CP16(base + so,               Ahp + ga);
            CP16(base + TILEB + so,       Alp + ga);
            CP16(base + 2u * TILEB + so,  Bhp + gb);
            CP16(base + 3u * TILEB + so,  Blp + gb);
        }
    };

    auto load_frags = [&](uint32_t base, uint32_t kb, uint32_t* F) {
        const uint32_t aHi = base,              aLo = base + TILEB;
        const uint32_t bHi = base + 2u * TILEB, bLo = base + 3u * TILEB;
        #pragma unroll
        for (int mf = 0; mf < 2; mf++) {
            uint32_t ad = aHi + aOff + (uint32_t)mf * (16u * ROWB) + kb;
            LDSM4(F[mf*4+0], F[mf*4+1], F[mf*4+2], F[mf*4+3], ad);
            uint32_t al = aLo + aOff + (uint32_t)mf * (16u * ROWB) + kb;
            LDSM4(F[8+mf*4+0], F[8+mf*4+1], F[8+mf*4+2], F[8+mf*4+3], al);
        }
        #pragma unroll
        for (int bf = 0; bf < 4; bf++) {
            uint32_t bd = bHi + bOff + (uint32_t)bf * (16u * ROWB) + kb;
            LDSM4(F[16+bf*4+0], F[16+bf*4+1], F[16+bf*4+2], F[16+bf*4+3], bd);
            uint32_t bl = bLo + bOff + (uint32_t)bf * (16u * ROWB) + kb;
            LDSM4(F[32+bf*4+0], F[32+bf*4+1], F[32+bf*4+2], F[32+bf*4+3], bl);
        }
    };

    // TERM-MAJOR: all hi*hi, then all hi*lo, then all lo*hi. Dependent MMAs
    // on the same accumulator are separated by 15 independent MMAs.
    auto mma_step = [&](const uint32_t* F) {
        #pragma unroll
        for (int mf = 0; mf < 2; mf++)
            #pragma unroll
            for (int nf = 0; nf < 8; nf++) {
                const uint32_t* BhF = F_BH(F, nf >> 1);
                uint32_t bh[2] = { BhF[(nf & 1) ? 2 : 0], BhF[(nf & 1) ? 3 : 1] };
                MMA16816(acc[mf][nf], F_AH(F, mf), bh);      // hi*hi
            }
        #pragma unroll
        for (int mf = 0; mf < 2; mf++)
            #pragma unroll
            for (int nf = 0; nf < 8; nf++) {
                const uint32_t* BlF = F_BL(F, nf >> 1);
                uint32_t bl2[2] = { BlF[(nf & 1) ? 2 : 0], BlF[(nf & 1) ? 3 : 1] };
                MMA16816(acc[mf][nf], F_AH(F, mf), bl2);     // hi*lo
            }
        #pragma unroll
        for (int mf = 0; mf < 2; mf++)
            #pragma unroll
            for (int nf = 0; nf < 8; nf++) {
                const uint32_t* BhF = F_BH(F, nf >> 1);
                uint32_t bh[2] = { BhF[(nf & 1) ? 2 : 0], BhF[(nf & 1) ? 3 : 1] };
                MMA16816(acc[mf][nf], F_AL(F, mf), bh);      // lo*hi
            }
    };

    #pragma unroll
    for (int s = 0; s < NST - 1; s++) { issue_stage(s); CP_COMMIT(); }

    uint32_t Fr[2][48];

    for (int kt = 0; kt < nk; kt++) {
        CP_WAIT();
        __syncthreads();

        const uint32_t base = sb + (uint32_t)(kt % NST) * STAGEB;

        load_frags(base, 0u, Fr[0]);          // ks=0 fragments

        if (kt + NST - 1 < nk) issue_stage(kt + NST - 1);
        CP_COMMIT();

        #pragma unroll
        for (int ks = 0; ks < 4; ks++) {
            if (ks < 3)
                load_frags(base, (uint32_t)(ks + 1) * 32u, Fr[(ks + 1) & 1]);
            mma_step(Fr[ks & 1]);
        }
    }

    // ---- epilogue ----
    const int g  = lane >> 2;
    const int tg = lane & 3;
    #pragma unroll
    for (int mf = 0; mf < 2; mf++) {
        const int r0 = bm + warpm * 32 + mf * 16 + g;
        #pragma unroll
        for (int nf = 0; nf < 8; nf++) {
            const int col = bn + warpn * 64 + nf * 8 + tg * 2;
            float v0 = acc[mf][nf][0], v1 = acc[mf][nf][1];
            float v2 = acc[mf][nf][2], v3 = acc[mf][nf][3];

            if (Cpart) {
                float* base2 = Cpart + (size_t)blockIdx.z * ((size_t)M * N);
                *(float2*)(base2 + (size_t)r0 * N + col)       = make_float2(v0, v1);
                *(float2*)(base2 + (size_t)(r0 + 8) * N + col) = make_float2(v2, v3);
                continue;
            }
            if (colscale) {
                float s0 = colscale[col], s1 = colscale[col + 1];
                v0 *= s0; v1 *= s1; v2 *= s0; v3 *= s1;
            }
            if (bias) {
                float b0 = bias[col], b1 = bias[col + 1];
                v0 += b0; v1 += b1; v2 += b0; v3 += b1;
            }
            if (do_relu) {
                v0 = fmaxf(v0, 0.0f); v1 = fmaxf(v1, 0.0f);
                v2 = fmaxf(v2, 0.0f); v3 = fmaxf(v3, 0.0f);
            }
            if (Cf) {      // final: N==512; cols [0,256) mu, [256,512) logvar
                float* p0;
                float* p1;
                if (col < 256) {
                    p0 = Cf + (size_t)r0 * 256 + col;
                    p1 = Cf + (size_t)(r0 + 8) * 256 + col;
                } else {
                    float* half2 = Cf + (size_t)BATCH * 256;
                    p0 = half2 + (size_t)r0 * 256 + (col - 256);
                    p1 = half2 + (size_t)(r0 + 8) * 256 + (col - 256);
                }
                *(float2*)p0 = make_float2(v0, v1);
                *(float2*)p1 = make_float2(v2, v3);
            } else {
                __nv_bfloat16 h0, h1, h2, h3, l0, l1, l2, l3;
                bsplit(v0, h0, l0); bsplit(v1, h1, l1);
                bsplit(v2, h2, l2); bsplit(v3, h3, l3);
                *(uint32_t*)(Ch + (size_t)r0 * N + col)       = packbf(h0, h1);
                *(uint32_t*)(Cl + (size_t)r0 * N + col)       = packbf(l0, l1);
                *(uint32_t*)(Ch + (size_t)(r0 + 8) * N + col) = packbf(h2, h3);
                *(uint32_t*)(Cl + (size_t)(r0 + 8) * N + col) = packbf(l2, l3);
            }
        }
    }
}

// ---------------------------------------------------------------------------
// Launch
// ---------------------------------------------------------------------------
extern "C" void kernel_launch(void* const* d_in, const int* in_sizes, int n_in,
                              void* d_out, int out_size)
{
    const float* x   = (const float*)d_in[0];
    const float* fw  = (const float*)d_in[1];
    const float* kp  = (const float*)d_in[2];
    const float* W1  = (const float*)d_in[3];
    const float* b1  = (const float*)d_in[4];
    const float* W2  = (const float*)d_in[5];
    const float* b2  = (const float*)d_in[6];
    const float* Wmu = (const float*)d_in[7];
    const float* bmu = (const float*)d_in[8];
    const float* Wlv = (const float*)d_in[9];
    const float* blv = (const float*)d_in[10];
    float* out = (float*)d_out;

    __nv_bfloat16 *Dt_h, *Dt_l, *Dm_h, *Dm_l, *W1_h, *W1_l, *A1_h, *A1_l;
    __nv_bfloat16 *W1e_h, *W1e_l, *x_h, *x_l, *h1_h, *h1_l;
    __nv_bfloat16 *W2_h, *W2_l, *h2_h, *h2_l, *Wml_h, *Wml_l;
    float *bml, *bscale, *part;
    cudaGetSymbolAddress((void**)&Dt_h,  g_Dt_hi);  cudaGetSymbolAddress((void**)&Dt_l,  g_Dt_lo);
    cudaGetSymbolAddress((void**)&Dm_h,  g_Dm_hi);  cudaGetSymbolAddress((void**)&Dm_l,  g_Dm_lo);
    cudaGetSymbolAddress((void**)&W1_h,  g_W1_hi);  cudaGetSymbolAddress((void**)&W1_l,  g_W1_lo);
    cudaGetSymbolAddress((void**)&A1_h,  g_A1_hi);  cudaGetSymbolAddress((void**)&A1_l,  g_A1_lo);
    cudaGetSymbolAddress((void**)&W1e_h, g_W1e_hi); cudaGetSymbolAddress((void**)&W1e_l, g_W1e_lo);
    cudaGetSymbolAddress((void**)&x_h,   g_x_hi);   cudaGetSymbolAddress((void**)&x_l,   g_x_lo);
    cudaGetSymbolAddress((void**)&h1_h,  g_h1_hi);  cudaGetSymbolAddress((void**)&h1_l,  g_h1_lo);
    cudaGetSymbolAddress((void**)&W2_h,  g_W2_hi);  cudaGetSymbolAddress((void**)&W2_l,  g_W2_lo);
    cudaGetSymbolAddress((void**)&h2_h,  g_h2_hi);  cudaGetSymbolAddress((void**)&h2_l,  g_h2_lo);
    cudaGetSymbolAddress((void**)&Wml_h, g_Wml_hi); cudaGetSymbolAddress((void**)&Wml_l, g_Wml_lo);
    cudaGetSymbolAddress((void**)&bml,   g_bml);
    cudaGetSymbolAddress((void**)&bscale, g_bscale);
    cudaGetSymbolAddress((void**)&part,  g_part);

    cudaFuncSetAttribute(gemm_bf16x3,
                         cudaFuncAttributeMaxDynamicSharedMemorySize, SMEM_GEMM);

    build_scale_kernel<<<8, 256>>>(fw, kp);
    build_D_kernel<<<(DIMN * DIMN) / 256, 256>>>();

    convert_split<<<(BATCH * DIMN / 8 + 255) / 256, 256>>>(x, x_h, x_l, BATCH * DIMN);
    convert_split<<<(1024 * DIMN / 8 + 255) / 256, 256>>>(W1, W1_h, W1_l, 1024 * DIMN);
    convert_split<<<(512 * 1024 / 8 + 255) / 256, 256>>>(W2, W2_h, W2_l, 512 * 1024);
    convert_split<<<(256 * 512 / 8 + 255) / 256, 256>>>(Wmu, Wml_h, Wml_l, 256 * 512);
    convert_split<<<(256 * 512 / 8 + 255) / 256, 256>>>(Wlv, Wml_h + 256 * 512,
                                                        Wml_l + 256 * 512, 256 * 512);
    merge_bias<<<2, 256>>>(bmu, blv);

    const int nW = 1024 * DIMN;

    // A1[j][kf] = (sum_n W1[j][n] * D[kf][n]) * bscale[kf]   (split-K=4)
    gemm_bf16x3<<<dim3(16, 8, 4), 256, SMEM_GEMM>>>(
        W1_h, W1_l, Dm_h, Dm_l, nullptr, nullptr, nullptr, nullptr, nullptr,
        part, 1024, 2048, 2048, 512, 0);
    reduce4_split<<<(nW / 4 + 255) / 256, 256>>>(part, bscale, A1_h, A1_l, nW, 2048);

    // W1e[j][m] = sum_kf A1[j][kf] * Dt[m][kf]               (split-K=4)
    gemm_bf16x3<<<dim3(16, 8, 4), 256, SMEM_GEMM>>>(
        A1_h, A1_l, Dt_h, Dt_l, nullptr, nullptr, nullptr, nullptr, nullptr,
        part, 1024, 2048, 2048, 512, 0);
    reduce4_split<<<(nW / 4 + 255) / 256, 256>>>(part, nullptr, W1e_h, W1e_l, nW, 2048);

    // h1 = relu(x @ W1e^T + b1)
    gemm_bf16x3<<<dim3(8, 128, 1), 256, SMEM_GEMM>>>(
        x_h, x_l, W1e_h, W1e_l, b1, nullptr, h1_h, h1_l, nullptr, nullptr,
        BATCH, 1024, 2048, 2048, 1);
    // h2 = relu(h1 @ W2^T + b2)
    gemm_bf16x3<<<dim3(4, 128, 1), 256, SMEM_GEMM>>>(
        h1_h, h1_l, W2_h, W2_l, b2, nullptr, h2_h, h2_l, nullptr, nullptr,
        BATCH, 512, 1024, 1024, 1);
    // [mu | logvar] = h2 @ [Wmu;Wlv]^T + [bmu;blv]
    gemm_bf16x3<<<dim3(4, 128, 1), 256, SMEM_GEMM>>>(
        h2_h, h2_l, Wml_h, Wml_l, bml, nullptr, nullptr, nullptr, out, nullptr,
        BATCH, 512, 512, 512, 0);
}

// round 9
// speedup vs baseline: 1.3240x; 1.3240x over previous
#include <cuda_runtime.h>
#include <cuda_bf16.h>
#include <cuda_fp16.h>
#include <math.h>
#include <stdint.h>

// Problem constants
#define DIMN  2048
#define BATCH 16384

// GEMM tiling (shared by both GEMM kernels)
#define BM    128
#define BN    128
#define BK    64
#define ROWB  144u                    // 128B data + 16B pad -> conflict-free LDSM
#define TILEB (128u * ROWB)           // 18432 B per 128x64 16-bit tile
// bf16x3 weight GEMM: 4 tiles/stage, 3 stages
#define NST   3
#define STAGEB (4u * TILEB)
#define SMEM_GEMM (NST * STAGEB)      // 221184 B
// f16x2 activation GEMM: 3 tiles/stage, 4 stages
#define NST2  4
#define STAGEB2 (3u * TILEB)
#define SMEM_GEMM2 (NST2 * STAGEB2)   // 221184 B

// ---------------------------------------------------------------------------
// Device scratch (static — no runtime allocs)
// ---------------------------------------------------------------------------
__device__ __align__(128) __nv_bfloat16 g_Dt_hi [DIMN * DIMN];
__device__ __align__(128) __nv_bfloat16 g_Dt_lo [DIMN * DIMN];
__device__ __align__(128) __nv_bfloat16 g_Dm_hi [DIMN * DIMN];
__device__ __align__(128) __nv_bfloat16 g_Dm_lo [DIMN * DIMN];
__device__ __align__(128) __nv_bfloat16 g_W1_hi [1024 * DIMN];
__device__ __align__(128) __nv_bfloat16 g_W1_lo [1024 * DIMN];
__device__ __align__(128) __nv_bfloat16 g_A1_hi [1024 * DIMN];
__device__ __align__(128) __nv_bfloat16 g_A1_lo [1024 * DIMN];
__device__ __align__(128) float g_part[4 * 1024 * DIMN];   // split-K partials
// fp16 activation-path arrays
__device__ __align__(128) __half g_x16   [BATCH * DIMN];
__device__ __align__(128) __half g_h1_16 [BATCH * 1024];
__device__ __align__(128) __half g_h2_16 [BATCH * 512];
__device__ __align__(128) __half g_W1ef_hi[1024 * DIMN];
__device__ __align__(128) __half g_W1ef_lo[1024 * DIMN];
__device__ __align__(128) __half g_W2f_hi [512 * 1024];
__device__ __align__(128) __half g_W2f_lo [512 * 1024];
__device__ __align__(128) __half g_Wmlf_hi[512 * 512];
__device__ __align__(128) __half g_Wmlf_lo[512 * 512];
__device__ float g_bml[512];
__device__ float g_bscale[DIMN];

// ---------------------------------------------------------------------------
// Band-scale (verified round 1)
// ---------------------------------------------------------------------------
__global__ void build_scale_kernel(const float* __restrict__ fw,
                                   const float* __restrict__ kptr)
{
    int idx = blockIdx.x * blockDim.x + threadIdx.x;
    if (idx >= DIMN) return;
    const float kv = *kptr;
    float val = 1.0f;
    const double step = 2047.0 / 30.0;
    #pragma unroll 1
    for (int i = 0; i < 30; i++) {
        int s = (int)(step * (double)i);
        int e = (i == 29) ? 2047 : (int)(step * (double)(i + 1));
        if (idx >= s && idx < e) {
            float f;
            if (e <= 30) f = 1.0f + fw[i] * kv * (1.0f - (float)i / 30.0f);
            else         f = 1.0f - fw[i] * kv * (1.0f - (float)(i - 30) / 30.0f);
            val = f;
        }
    }
    g_bscale[idx] = val;
}

static __device__ __forceinline__ void bsplit(float v, __nv_bfloat16& h, __nv_bfloat16& l)
{
    h = __float2bfloat16_rn(v);
    l = __float2bfloat16_rn(v - __bfloat162float(h));
}

static __device__ __forceinline__ uint32_t packbf(__nv_bfloat16 a, __nv_bfloat16 b)
{
    __nv_bfloat162 t(a, b);
    return *reinterpret_cast<uint32_t*>(&t);
}

static __device__ __forceinline__ void hsplit(float v, __half& h, __half& l)
{
    h = __float2half_rn(v);
    l = __float2half_rn(v - __half2float(h));
}

static __device__ __forceinline__ uint32_t packh(float a, float b)
{
    __half2 t = __floats2half2_rn(a, b);
    return *reinterpret_cast<uint32_t*>(&t);
}

static __device__ __forceinline__ uint32_t packh2(__half a, __half b)
{
    __half2 t(a, b);
    return *reinterpret_cast<uint32_t*>(&t);
}

// ---------------------------------------------------------------------------
// Build Dt (D^T) and Dm (D) as bf16 hi/lo (verified round 4)
// ---------------------------------------------------------------------------
__global__ void build_D_kernel()
{
    int idx = blockIdx.x * blockDim.x + threadIdx.x;
    int r = idx >> 11;
    int c = idx & (DIMN - 1);
    const float n0 = 0.022097086912079612f;  // sqrt(1/2048)
    const float n1 = 0.03125f;               // sqrt(2/2048)

    int q1 = ((2 * r + 1) * c) & 8191;
    float v1 = cospif((float)q1 * (1.0f / 4096.0f)) * ((c == 0) ? n0 : n1);
    bsplit(v1, g_Dt_hi[idx], g_Dt_lo[idx]);

    int q2 = ((2 * c + 1) * r) & 8191;
    float v2 = cospif((float)q2 * (1.0f / 4096.0f)) * ((r == 0) ? n0 : n1);
    bsplit(v2, g_Dm_hi[idx], g_Dm_lo[idx]);
}

// ---------------------------------------------------------------------------
// fp32 -> bf16 hi/lo split (verified round 7)
// ---------------------------------------------------------------------------
__global__ void convert_split(const float* __restrict__ s,
                              __nv_bfloat16* __restrict__ hi,
                              __nv_bfloat16* __restrict__ lo, int n)
{
    int i = (blockIdx.x * blockDim.x + threadIdx.x) << 3;
    if (i >= n) return;
    float4 v0 = *(const float4*)(s + i);
    float4 v1 = *(const float4*)(s + i + 4);
    __nv_bfloat16 h0, h1, h2, h3, h4, h5, h6, h7;
    __nv_bfloat16 l0, l1, l2, l3, l4, l5, l6, l7;
    bsplit(v0.x, h0, l0); bsplit(v0.y, h1, l1);
    bsplit(v0.z, h2, l2); bsplit(v0.w, h3, l3);
    bsplit(v1.x, h4, l4); bsplit(v1.y, h5, l5);
    bsplit(v1.z, h6, l6); bsplit(v1.w, h7, l7);
    uint4 hbuf, lbuf;
    hbuf.x = packbf(h0, h1); hbuf.y = packbf(h2, h3);
    hbuf.z = packbf(h4, h5); hbuf.w = packbf(h6, h7);
    lbuf.x = packbf(l0, l1); lbuf.y = packbf(l2, l3);
    lbuf.z = packbf(l4, l5); lbuf.w = packbf(l6, l7);
    *(uint4*)(hi + i) = hbuf;
    *(uint4*)(lo + i) = lbuf;
}

// fp32 -> fp16 single (activations)
__global__ void convert_f16(const float* __restrict__ s,
                            __half* __restrict__ d, int n)
{
    int i = (blockIdx.x * blockDim.x + threadIdx.x) << 3;
    if (i >= n) return;
    float4 v0 = *(const float4*)(s + i);
    float4 v1 = *(const float4*)(s + i + 4);
    uint4 buf;
    buf.x = packh(v0.x, v0.y); buf.y = packh(v0.z, v0.w);
    buf.z = packh(v1.x, v1.y); buf.w = packh(v1.z, v1.w);
    *(uint4*)(d + i) = buf;
}

// fp32 -> fp16 hi/lo split (weights for activation GEMMs)
__global__ void convert_split_f16(const float* __restrict__ s,
                                  __half* __restrict__ hi,
                                  __half* __restrict__ lo, int n)
{
    int i = (blockIdx.x * blockDim.x + threadIdx.x) << 3;
    if (i >= n) return;
    float4 v0 = *(const float4*)(s + i);
    float4 v1 = *(const float4*)(s + i + 4);
    __half h0, h1, h2, h3, h4, h5, h6, h7;
    __half l0, l1, l2, l3, l4, l5, l6, l7;
    hsplit(v0.x, h0, l0); hsplit(v0.y, h1, l1);
    hsplit(v0.z, h2, l2); hsplit(v0.w, h3, l3);
    hsplit(v1.x, h4, l4); hsplit(v1.y, h5, l5);
    hsplit(v1.z, h6, l6); hsplit(v1.w, h7, l7);
    uint4 hbuf, lbuf;
    hbuf.x = packh2(h0, h1); hbuf.y = packh2(h2, h3);
    hbuf.z = packh2(h4, h5); hbuf.w = packh2(h6, h7);
    lbuf.x = packh2(l0, l1); lbuf.y = packh2(l2, l3);
    lbuf.z = packh2(l4, l5); lbuf.w = packh2(l6, l7);
    *(uint4*)(hi + i) = hbuf;
    *(uint4*)(lo + i) = lbuf;
}

// sum 4 split-K fp32 partials -> (optional colscale) -> bf16 hi/lo
__global__ void reduce4_split(const float* __restrict__ part,
                              const float* __restrict__ colscale,
                              __nv_bfloat16* __restrict__ hi,
                              __nv_bfloat16* __restrict__ lo,
                              int n, int N)
{
    int i = (blockIdx.x * blockDim.x + threadIdx.x) << 2;
    if (i >= n) return;
    float4 a = *(const float4*)(part + i);
    float4 b = *(const float4*)(part + (size_t)n + i);
    float4 c = *(const float4*)(part + 2 * (size_t)n + i);
    float4 d = *(const float4*)(part + 3 * (size_t)n + i);
    float v0 = (a.x + b.x) + (c.x + d.x);
    float v1 = (a.y + b.y) + (c.y + d.y);
    float v2 = (a.z + b.z) + (c.z + d.z);
    float v3 = (a.w + b.w) + (c.w + d.w);
    if (colscale) {
        int col = i & (N - 1);
        v0 *= colscale[col];     v1 *= colscale[col + 1];
        v2 *= colscale[col + 2]; v3 *= colscale[col + 3];
    }
    __nv_bfloat16 h0, h1, h2, h3, l0, l1, l2, l3;
    bsplit(v0, h0, l0); bsplit(v1, h1, l1);
    bsplit(v2, h2, l2); bsplit(v3, h3, l3);
    __nv_bfloat162 hp0(h0, h1), hp1(h2, h3), lp0(l0, l1), lp1(l2, l3);
    *(__nv_bfloat162*)(hi + i)     = hp0;
    *(__nv_bfloat162*)(hi + i + 2) = hp1;
    *(__nv_bfloat162*)(lo + i)     = lp0;
    *(__nv_bfloat162*)(lo + i + 2) = lp1;
}

// sum 4 split-K fp32 partials -> fp16 hi/lo (W1e for activation GEMM)
__global__ void reduce4_split_f16(const float* __restrict__ part,
                                  __half* __restrict__ hi,
                                  __half* __restrict__ lo, int n)
{
    int i = (blockIdx.x * blockDim.x + threadIdx.x) << 2;
    if (i >= n) return;
    float4 a = *(const float4*)(part + i);
    float4 b = *(const float4*)(part + (size_t)n + i);
    float4 c = *(const float4*)(part + 2 * (size_t)n + i);
    float4 d = *(const float4*)(part + 3 * (size_t)n + i);
    float v0 = (a.x + b.x) + (c.x + d.x);
    float v1 = (a.y + b.y) + (c.y + d.y);
    float v2 = (a.z + b.z) + (c.z + d.z);
    float v3 = (a.w + b.w) + (c.w + d.w);
    __half h0, h1, h2, h3, l0, l1, l2, l3;
    hsplit(v0, h0, l0); hsplit(v1, h1, l1);
    hsplit(v2, h2, l2); hsplit(v3, h3, l3);
    uint2 hb, lb;
    hb.x = packh2(h0, h1); hb.y = packh2(h2, h3);
    lb.x = packh2(l0, l1); lb.y = packh2(l2, l3);
    *(uint2*)(hi + i) = hb;
    *(uint2*)(lo + i) = lb;
}

__global__ void merge_bias(const float* __restrict__ bmu, const float* __restrict__ blv)
{
    int i = blockIdx.x * blockDim.x + threadIdx.x;
    if (i < 256)      g_bml[i] = bmu[i];
    else if (i < 512) g_bml[i] = blv[i - 256];
}

// ---------------------------------------------------------------------------
// mma.sync / ldmatrix / cp.async helpers
// ---------------------------------------------------------------------------
#define LDSM4(r0, r1, r2, r3, addr)                                            \
    asm volatile("ldmatrix.sync.aligned.m8n8.x4.shared.b16 {%0,%1,%2,%3}, [%4];" \
                 : "=r"(r0), "=r"(r1), "=r"(r2), "=r"(r3) : "r"(addr))

#define MMA_BF16(c, a, b)                                                      \
    asm volatile("mma.sync.aligned.m16n8k16.row.col.f32.bf16.bf16.f32 "        \
                 "{%0,%1,%2,%3},{%4,%5,%6,%7},{%8,%9},{%0,%1,%2,%3};"          \
                 : "+f"((c)[0]), "+f"((c)[1]), "+f"((c)[2]), "+f"((c)[3])      \
                 : "r"((a)[0]), "r"((a)[1]), "r"((a)[2]), "r"((a)[3]),         \
                   "r"((b)[0]), "r"((b)[1]))

#define MMA_F16(c, a, b)                                                       \
    asm volatile("mma.sync.aligned.m16n8k16.row.col.f32.f16.f16.f32 "          \
                 "{%0,%1,%2,%3},{%4,%5,%6,%7},{%8,%9},{%0,%1,%2,%3};"          \
                 : "+f"((c)[0]), "+f"((c)[1]), "+f"((c)[2]), "+f"((c)[3])      \
                 : "r"((a)[0]), "r"((a)[1]), "r"((a)[2]), "r"((a)[3]),         \
                   "r"((b)[0]), "r"((b)[1]))

#define CP16(sa, ga)                                                           \
    asm volatile("cp.async.cg.shared.global [%0], [%1], 16;"                   \
                 :: "r"(sa), "l"(ga) : "memory")
#define CP_COMMIT() asm volatile("cp.async.commit_group;" ::: "memory")
#define CP_WAIT(nn)  asm volatile("cp.async.wait_group %0;" :: "n"(nn) : "memory")

// ---------------------------------------------------------------------------
// bf16x3 tensor-core NT GEMM (weight prep; verified rounds 5-8), split-K.
// ---------------------------------------------------------------------------
__global__ __launch_bounds__(256, 1)
void gemm_bf16x3(const __nv_bfloat16* __restrict__ Ahp,
                 const __nv_bfloat16* __restrict__ Alp,
                 const __nv_bfloat16* __restrict__ Bhp,
                 const __nv_bfloat16* __restrict__ Blp,
                 float* __restrict__ Cpart,
                 int M, int N, int K, int klen)
{
    extern __shared__ __align__(1024) char smem[];
    const uint32_t sb = (uint32_t)__cvta_generic_to_shared(smem);

    const int tid   = threadIdx.x;
    const int lane  = tid & 31;
    const int wid   = tid >> 5;
    const int warpm = wid & 3;
    const int warpn = wid >> 2;
    const int bm = blockIdx.y * BM;
    const int bn = blockIdx.x * BN;
    const int kbase = blockIdx.z * klen;

    const uint32_t aOff = (uint32_t)(warpm * 32 + (lane & 15)) * ROWB
                        + (uint32_t)(lane >> 4) * 16u;
    const uint32_t bOff = (uint32_t)(warpn * 64 + (lane & 7) + ((lane & 16) ? 8 : 0)) * ROWB
                        + (uint32_t)((lane >> 3) & 1) * 16u;

    float acc[2][8][4];
    #pragma unroll
    for (int i = 0; i < 2; i++)
        #pragma unroll
        for (int j = 0; j < 8; j++)
            #pragma unroll
            for (int q = 0; q < 4; q++) acc[i][j][q] = 0.0f;

    const int nk = klen >> 6;

    auto issue_stage = [&](int kt) {
        const uint32_t base = sb + (uint32_t)(kt % NST) * STAGEB;
        const size_t kof = (size_t)kbase + (size_t)kt * BK;
        #pragma unroll
        for (int h = 0; h < 4; h++) {
            const int c   = tid + h * 256;
            const int row = c >> 3;
            const int q   = c & 7;
            const uint32_t so = (uint32_t)row * ROWB + (uint32_t)q * 16u;
            const size_t ga = (size_t)(bm + row) * K + kof + (size_t)q * 8;
            const size_t gb = (size_t)(bn + row) * K + kof + (size_t)q * 8;
            CP16(base + so,               Ahp + ga);
            CP16(base + TILEB + so,       Alp + ga);
            CP16(base + 2u * TILEB + so,  Bhp + gb);
            CP16(base + 3u * TILEB + so,  Blp + gb);
        }
    };

    auto load_frags = [&](uint32_t base, uint32_t kb, uint32_t* F) {
        const uint32_t aHi = base,              aLo = base + TILEB;
        const uint32_t bHi = base + 2u * TILEB, bLo = base + 3u * TILEB;
        #pragma unroll
        for (int mf = 0; mf < 2; mf++) {
            uint32_t ad = aHi + aOff + (uint32_t)mf * (16u * ROWB) + kb;
            LDSM4(F[mf*4+0], F[mf*4+1], F[mf*4+2], F[mf*4+3], ad);
            uint32_t al = aLo + aOff + (uint32_t)mf * (16u * ROWB) + kb;
            LDSM4(F[8+mf*4+0], F[8+mf*4+1], F[8+mf*4+2], F[8+mf*4+3], al);
        }
        #pragma unroll
        for (int bf = 0; bf < 4; bf++) {
            uint32_t bd = bHi + bOff + (uint32_t)bf * (16u * ROWB) + kb;
            LDSM4(F[16+bf*4+0], F[16+bf*4+1], F[16+bf*4+2], F[16+bf*4+3], bd);
            uint32_t bl = bLo + bOff + (uint32_t)bf * (16u * ROWB) + kb;
            LDSM4(F[32+bf*4+0], F[32+bf*4+1], F[32+bf*4+2], F[32+bf*4+3], bl);
        }
    };

    auto mma_step = [&](const uint32_t* F) {
        #pragma unroll
        for (int mf = 0; mf < 2; mf++)
            #pragma unroll
            for (int nf = 0; nf < 8; nf++) {
                const uint32_t* BhF = &F[16 + (nf >> 1) * 4];
                uint32_t bh[2] = { BhF[(nf & 1) ? 2 : 0], BhF[(nf & 1) ? 3 : 1] };
                MMA_BF16(acc[mf][nf], &F[mf * 4], bh);        // hi*hi
            }
        #pragma unroll
        for (int mf = 0; mf < 2; mf++)
            #pragma unroll
            for (int nf = 0; nf < 8; nf++) {
                const uint32_t* BlF = &F[32 + (nf >> 1) * 4];
                uint32_t bl2[2] = { BlF[(nf & 1) ? 2 : 0], BlF[(nf & 1) ? 3 : 1] };
                MMA_BF16(acc[mf][nf], &F[mf * 4], bl2);       // hi*lo
            }
        #pragma unroll
        for (int mf = 0; mf < 2; mf++)
            #pragma unroll
            for (int nf = 0; nf < 8; nf++) {
                const uint32_t* BhF = &F[16 + (nf >> 1) * 4];
                uint32_t bh[2] = { BhF[(nf & 1) ? 2 : 0], BhF[(nf & 1) ? 3 : 1] };
                MMA_BF16(acc[mf][nf], &F[8 + mf * 4], bh);    // lo*hi
            }
    };

    #pragma unroll
    for (int s = 0; s < NST - 1; s++) { issue_stage(s); CP_COMMIT(); }

    uint32_t Fr[2][48];

    for (int kt = 0; kt < nk; kt++) {
        CP_WAIT(NST - 2);
        __syncthreads();
        const uint32_t base = sb + (uint32_t)(kt % NST) * STAGEB;
        load_frags(base, 0u, Fr[0]);
        if (kt + NST - 1 < nk) issue_stage(kt + NST - 1);
        CP_COMMIT();
        #pragma unroll
        for (int ks = 0; ks < 4; ks++) {
            if (ks < 3)
                load_frags(base, (uint32_t)(ks + 1) * 32u, Fr[(ks + 1) & 1]);
            mma_step(Fr[ks & 1]);
        }
    }

    // fp32 split-K partial epilogue
    const int g  = lane >> 2;
    const int tg = lane & 3;
    float* base2 = Cpart + (size_t)blockIdx.z * ((size_t)M * N);
    #pragma unroll
    for (int mf = 0; mf < 2; mf++) {
        const int r0 = bm + warpm * 32 + mf * 16 + g;
        #pragma unroll
        for (int nf = 0; nf < 8; nf++) {
            const int col = bn + warpn * 64 + nf * 8 + tg * 2;
            *(float2*)(base2 + (size_t)r0 * N + col) =
                make_float2(acc[mf][nf][0], acc[mf][nf][1]);
            *(float2*)(base2 + (size_t)(r0 + 8) * N + col) =
                make_float2(acc[mf][nf][2], acc[mf][nf][3]);
        }
    }
}

// ---------------------------------------------------------------------------
// f16x2 activation GEMM: C[m][n] = sum_k A[m][k]*(Bh+Bl)[n][k]  (2 MMAs/acc)
// A: fp16 single; B: fp16 hi/lo. Output: fp16 single (Cs) w/ bias+relu,
// or fp32 final (Cf, mu/logvar mapping, N==512).
// ---------------------------------------------------------------------------
__global__ __launch_bounds__(256, 1)
void gemm_f16x2(const __half* __restrict__ Ap,
                const __half* __restrict__ Bhp,
                const __half* __restrict__ Blp,
                const float* __restrict__ bias,
                __half* __restrict__ Cs,
                float* __restrict__ Cf,
                int M, int N, int K, int do_relu)
{
    extern __shared__ __align__(1024) char smem[];
    const uint32_t sb = (uint32_t)__cvta_generic_to_shared(smem);

    const int tid   = threadIdx.x;
    const int lane  = tid & 31;
    const int wid   = tid >> 5;
    const int warpm = wid & 3;
    const int warpn = wid >> 2;
    const int bm = blockIdx.y * BM;
    const int bn = blockIdx.x * BN;

    const uint32_t aOff = (uint32_t)(warpm * 32 + (lane & 15)) * ROWB
                        + (uint32_t)(lane >> 4) * 16u;
    const uint32_t bOff = (uint32_t)(warpn * 64 + (lane & 7) + ((lane & 16) ? 8 : 0)) * ROWB
                        + (uint32_t)((lane >> 3) & 1) * 16u;

    float acc[2][8][4];
    #pragma unroll
    for (int i = 0; i < 2; i++)
        #pragma unroll
        for (int j = 0; j < 8; j++)
            #pragma unroll
            for (int q = 0; q < 4; q++) acc[i][j][q] = 0.0f;

    const int nk = K >> 6;

    auto issue_stage = [&](int kt) {
        const uint32_t base = sb + (uint32_t)(kt % NST2) * STAGEB2;
        const size_t kof = (size_t)kt * BK;
        #pragma unroll
        for (int h = 0; h < 4; h++) {
            const int c   = tid + h * 256;
            const int row = c >> 3;
            const int q   = c & 7;
            const uint32_t so = (uint32_t)row * ROWB + (uint32_t)q * 16u;
            const size_t ga = (size_t)(bm + row) * K + kof + (size_t)q * 8;
            const size_t gb = (size_t)(bn + row) * K + kof + (size_t)q * 8;
            CP16(base + so,               Ap  + ga);
            CP16(base + TILEB + so,       Bhp + gb);
            CP16(base + 2u * TILEB + so,  Blp + gb);
        }
    };

    // F[0..7]=A, F[8..23]=Bh, F[24..39]=Bl
    auto load_frags = [&](uint32_t base, uint32_t kb, uint32_t* F) {
        const uint32_t aT = base;
        const uint32_t bHi = base + TILEB, bLo = base + 2u * TILEB;
        #pragma unroll
        for (int mf = 0; mf < 2; mf++) {
            uint32_t ad = aT + aOff + (uint32_t)mf * (16u * ROWB) + kb;
            LDSM4(F[mf*4+0], F[mf*4+1], F[mf*4+2], F[mf*4+3], ad);
        }
        #pragma unroll
        for (int bf = 0; bf < 4; bf++) {
            uint32_t bd = bHi + bOff + (uint32_t)bf * (16u * ROWB) + kb;
            LDSM4(F[8+bf*4+0], F[8+bf*4+1], F[8+bf*4+2], F[8+bf*4+3], bd);
            uint32_t bl = bLo + bOff + (uint32_t)bf * (16u * ROWB) + kb;
            LDSM4(F[24+bf*4+0], F[24+bf*4+1], F[24+bf*4+2], F[24+bf*4+3], bl);
        }
    };

    auto mma_step = [&](const uint32_t* F) {
        #pragma unroll
        for (int mf = 0; mf < 2; mf++)
            #pragma unroll
            for (int nf = 0; nf < 8; nf++) {
                const uint32_t* BhF = &F[8 + (nf >> 1) * 4];
                uint32_t bh[2] = { BhF[(nf & 1) ? 2 : 0], BhF[(nf & 1) ? 3 : 1] };
                MMA_F16(acc[mf][nf], &F[mf * 4], bh);        // A*hi
            }
        #pragma unroll
        for (int mf = 0; mf < 2; mf++)
            #pragma unroll
            for (int nf = 0; nf < 8; nf++) {
                const uint32_t* BlF = &F[24 + (nf >> 1) * 4];
                uint32_t bl2[2] = { BlF[(nf & 1) ? 2 : 0], BlF[(nf & 1) ? 3 : 1] };
                MMA_F16(acc[mf][nf], &F[mf * 4], bl2);       // A*lo
            }
    };

    #pragma unroll
    for (int s = 0; s < NST2 - 1; s++) { issue_stage(s); CP_COMMIT(); }

    uint32_t Fr[2][40];

    for (int kt = 0; kt < nk; kt++) {
        CP_WAIT(NST2 - 2);
        __syncthreads();
        const uint32_t base = sb + (uint32_t)(kt % NST2) * STAGEB2;
        load_frags(base, 0u, Fr[0]);
        if (kt + NST2 - 1 < nk) issue_stage(kt + NST2 - 1);
        CP_COMMIT();
        #pragma unroll
        for (int ks = 0; ks < 4; ks++) {
            if (ks < 3)
                load_frags(base, (uint32_t)(ks + 1) * 32u, Fr[(ks + 1) & 1]);
            mma_step(Fr[ks & 1]);
        }
    }

    // ---- epilogue ----
    const int g  = lane >> 2;
    const int tg = lane & 3;
    #pragma unroll
    for (int mf = 0; mf < 2; mf++) {
        const int r0 = bm + warpm * 32 + mf * 16 + g;
        #pragma unroll
        for (int nf = 0; nf < 8; nf++) {
            const int col = bn + warpn * 64 + nf * 8 + tg * 2;
            float b0 = bias[col], b1 = bias[col + 1];
            float v0 = acc[mf][nf][0] + b0, v1 = acc[mf][nf][1] + b1;
            float v2 = acc[mf][nf][2] + b0, v3 = acc[mf][nf][3] + b1;
            if (do_relu) {
                v0 = fmaxf(v0, 0.0f); v1 = fmaxf(v1, 0.0f);
                v2 = fmaxf(v2, 0.0f); v3 = fmaxf(v3, 0.0f);
            }
            if (Cf) {      // final: N==512; cols [0,256) mu, [256,512) logvar
                float* p0;
                float* p1;
                if (col < 256) {
                    p0 = Cf + (size_t)r0 * 256 + col;
                    p1 = Cf + (size_t)(r0 + 8) * 256 + col;
                } else {
                    float* half2p = Cf + (size_t)BATCH * 256;
                    p0 = half2p + (size_t)r0 * 256 + (col - 256);
                    p1 = half2p + (size_t)(r0 + 8) * 256 + (col - 256);
                }
                *(float2*)p0 = make_float2(v0, v1);
                *(float2*)p1 = make_float2(v2, v3);
            } else {
                *(uint32_t*)(Cs + (size_t)r0 * N + col)       = packh(v0, v1);
                *(uint32_t*)(Cs + (size_t)(r0 + 8) * N + col) = packh(v2, v3);
            }
        }
    }
}

// ---------------------------------------------------------------------------
// Launch
// ---------------------------------------------------------------------------
extern "C" void kernel_launch(void* const* d_in, const int* in_sizes, int n_in,
                              void* d_out, int out_size)
{
    const float* x   = (const float*)d_in[0];
    const float* fw  = (const float*)d_in[1];
    const float* kp  = (const float*)d_in[2];
    const float* W1  = (const float*)d_in[3];
    const float* b1  = (const float*)d_in[4];
    const float* W2  = (const float*)d_in[5];
    const float* b2  = (const float*)d_in[6];
    const float* Wmu = (const float*)d_in[7];
    const float* bmu = (const float*)d_in[8];
    const float* Wlv = (const float*)d_in[9];
    const float* blv = (const float*)d_in[10];
    float* out = (float*)d_out;

    __nv_bfloat16 *Dt_h, *Dt_l, *Dm_h, *Dm_l, *W1_h, *W1_l, *A1_h, *A1_l;
    __half *x16, *h1_16, *h2_16, *W1ef_h, *W1ef_l, *W2f_h, *W2f_l, *Wmlf_h, *Wmlf_l;
    float *bml, *bscale, *part;
    cudaGetSymbolAddress((void**)&Dt_h,   g_Dt_hi);  cudaGetSymbolAddress((void**)&Dt_l,  g_Dt_lo);
    cudaGetSymbolAddress((void**)&Dm_h,   g_Dm_hi);  cudaGetSymbolAddress((void**)&Dm_l,  g_Dm_lo);
    cudaGetSymbolAddress((void**)&W1_h,   g_W1_hi);  cudaGetSymbolAddress((void**)&W1_l,  g_W1_lo);
    cudaGetSymbolAddress((void**)&A1_h,   g_A1_hi);  cudaGetSymbolAddress((void**)&A1_l,  g_A1_lo);
    cudaGetSymbolAddress((void**)&x16,    g_x16);
    cudaGetSymbolAddress((void**)&h1_16,  g_h1_16);
    cudaGetSymbolAddress((void**)&h2_16,  g_h2_16);
    cudaGetSymbolAddress((void**)&W1ef_h, g_W1ef_hi); cudaGetSymbolAddress((void**)&W1ef_l, g_W1ef_lo);
    cudaGetSymbolAddress((void**)&W2f_h,  g_W2f_hi);  cudaGetSymbolAddress((void**)&W2f_l,  g_W2f_lo);
    cudaGetSymbolAddress((void**)&Wmlf_h, g_Wmlf_hi); cudaGetSymbolAddress((void**)&Wmlf_l, g_Wmlf_lo);
    cudaGetSymbolAddress((void**)&bml,    g_bml);
    cudaGetSymbolAddress((void**)&bscale, g_bscale);
    cudaGetSymbolAddress((void**)&part,   g_part);

    cudaFuncSetAttribute(gemm_bf16x3,
                         cudaFuncAttributeMaxDynamicSharedMemorySize, SMEM_GEMM);
    cudaFuncSetAttribute(gemm_f16x2,
                         cudaFuncAttributeMaxDynamicSharedMemorySize, SMEM_GEMM2);

    build_scale_kernel<<<8, 256>>>(fw, kp);
    build_D_kernel<<<(DIMN * DIMN) / 256, 256>>>();

    convert_f16<<<(BATCH * DIMN / 8 + 255) / 256, 256>>>(x, x16, BATCH * DIMN);
    convert_split<<<(1024 * DIMN / 8 + 255) / 256, 256>>>(W1, W1_h, W1_l, 1024 * DIMN);
    convert_split_f16<<<(512 * 1024 / 8 + 255) / 256, 256>>>(W2, W2f_h, W2f_l, 512 * 1024);
    convert_split_f16<<<(256 * 512 / 8 + 255) / 256, 256>>>(Wmu, Wmlf_h, Wmlf_l, 256 * 512);
    convert_split_f16<<<(256 * 512 / 8 + 255) / 256, 256>>>(Wlv, Wmlf_h + 256 * 512,
                                                            Wmlf_l + 256 * 512, 256 * 512);
    merge_bias<<<2, 256>>>(bmu, blv);

    const int nW = 1024 * DIMN;

    // A1[j][kf] = (sum_n W1[j][n] * D[kf][n]) * bscale[kf]   (split-K=4, bf16x3)
    gemm_bf16x3<<<dim3(16, 8, 4), 256, SMEM_GEMM>>>(
        W1_h, W1_l, Dm_h, Dm_l, part, 1024, 2048, 2048, 512);
    reduce4_split<<<(nW / 4 + 255) / 256, 256>>>(part, bscale, A1_h, A1_l, nW, 2048);

    // W1e[j][m] = sum_kf A1[j][kf] * Dt[m][kf]               (split-K=4, bf16x3)
    gemm_bf16x3<<<dim3(16, 8, 4), 256, SMEM_GEMM>>>(
        A1_h, A1_l, Dt_h, Dt_l, part, 1024, 2048, 2048, 512);
    reduce4_split_f16<<<(nW / 4 + 255) / 256, 256>>>(part, W1ef_h, W1ef_l, nW);

    // h1 = relu(x @ W1e^T + b1)        (fp16 A x fp16x2 B, 2 MMAs)
    gemm_f16x2<<<dim3(8, 128), 256, SMEM_GEMM2>>>(
        x16, W1ef_h, W1ef_l, b1, h1_16, nullptr, BATCH, 1024, 2048, 1);
    // h2 = relu(h1 @ W2^T + b2)
    gemm_f16x2<<<dim3(4, 128), 256, SMEM_GEMM2>>>(
        h1_16, W2f_h, W2f_l, b2, h2_16, nullptr, BATCH, 512, 1024, 1);
    // [mu | logvar] = h2 @ [Wmu;Wlv]^T + [bmu;blv]
    gemm_f16x2<<<dim3(4, 128), 256, SMEM_GEMM2>>>(
        h2_16, Wmlf_h, Wmlf_l, bml, nullptr, out, BATCH, 512, 512, 0);
}

// round 10
// speedup vs baseline: 1.3991x; 1.0568x over previous
#include <cuda_runtime.h>
#include <cuda_bf16.h>
#include <cuda_fp16.h>
#include <math.h>
#include <stdint.h>

// Problem constants
#define DIMN  2048
#define BATCH 16384

// Shared tile constants
#define BK    64
#define ROWB  144u                    // 128B data + 16B pad -> conflict-free LDSM

// bf16x3 weight GEMM (verified R5-R9): 128x128 tile, 4 tiles/stage, 3 stages
#define BM    128
#define BN    128
#define TILEB (128u * ROWB)           // 18432 B per 128x64 16-bit tile
#define NST   3
#define STAGEB (4u * TILEB)
#define SMEM_GEMM (NST * STAGEB)      // 221184 B

// f16x2 activation GEMM v2: 128x64 tile, 2 CTAs/SM target
#define TILEB_A  (128u * ROWB)        // 18432
#define TILEB_B  (64u * ROWB)         // 9216
#define NST2     3
#define STAGEB2  (TILEB_A + 2u * TILEB_B)   // 36864
#define SMEM_GEMM2 (NST2 * STAGEB2)   // 110592 B -> 2 CTAs/SM

// ---------------------------------------------------------------------------
// Device scratch (static — no runtime allocs)
// ---------------------------------------------------------------------------
__device__ __align__(128) __nv_bfloat16 g_Dt_hi [DIMN * DIMN];
__device__ __align__(128) __nv_bfloat16 g_Dt_lo [DIMN * DIMN];
__device__ __align__(128) __nv_bfloat16 g_Dm_hi [DIMN * DIMN];
__device__ __align__(128) __nv_bfloat16 g_Dm_lo [DIMN * DIMN];
__device__ __align__(128) __nv_bfloat16 g_W1_hi [1024 * DIMN];
__device__ __align__(128) __nv_bfloat16 g_W1_lo [1024 * DIMN];
__device__ __align__(128) __nv_bfloat16 g_A1_hi [1024 * DIMN];
__device__ __align__(128) __nv_bfloat16 g_A1_lo [1024 * DIMN];
__device__ __align__(128) float g_part[4 * 1024 * DIMN];   // split-K partials
// fp16 activation-path arrays
__device__ __align__(128) __half g_x16   [BATCH * DIMN];
__device__ __align__(128) __half g_h1_16 [BATCH * 1024];
__device__ __align__(128) __half g_h2_16 [BATCH * 512];
__device__ __align__(128) __half g_W1ef_hi[1024 * DIMN];
__device__ __align__(128) __half g_W1ef_lo[1024 * DIMN];
__device__ __align__(128) __half g_W2f_hi [512 * 1024];
__device__ __align__(128) __half g_W2f_lo [512 * 1024];
__device__ __align__(128) __half g_Wmlf_hi[512 * 512];
__device__ __align__(128) __half g_Wmlf_lo[512 * 512];
__device__ float g_bml[512];
__device__ float g_bscale[DIMN];

// ---------------------------------------------------------------------------
// Band-scale (verified round 1)
// ---------------------------------------------------------------------------
__global__ void build_scale_kernel(const float* __restrict__ fw,
                                   const float* __restrict__ kptr)
{
    int idx = blockIdx.x * blockDim.x + threadIdx.x;
    if (idx >= DIMN) return;
    const float kv = *kptr;
    float val = 1.0f;
    const double step = 2047.0 / 30.0;
    #pragma unroll 1
    for (int i = 0; i < 30; i++) {
        int s = (int)(step * (double)i);
        int e = (i == 29) ? 2047 : (int)(step * (double)(i + 1));
        if (idx >= s && idx < e) {
            float f;
            if (e <= 30) f = 1.0f + fw[i] * kv * (1.0f - (float)i / 30.0f);
            else         f = 1.0f - fw[i] * kv * (1.0f - (float)(i - 30) / 30.0f);
            val = f;
        }
    }
    g_bscale[idx] = val;
}

static __device__ __forceinline__ void bsplit(float v, __nv_bfloat16& h, __nv_bfloat16& l)
{
    h = __float2bfloat16_rn(v);
    l = __float2bfloat16_rn(v - __bfloat162float(h));
}

static __device__ __forceinline__ uint32_t packbf(__nv_bfloat16 a, __nv_bfloat16 b)
{
    __nv_bfloat162 t(a, b);
    return *reinterpret_cast<uint32_t*>(&t);
}

static __device__ __forceinline__ void hsplit(float v, __half& h, __half& l)
{
    h = __float2half_rn(v);
    l = __float2half_rn(v - __half2float(h));
}

static __device__ __forceinline__ uint32_t packh(float a, float b)
{
    __half2 t = __floats2half2_rn(a, b);
    return *reinterpret_cast<uint32_t*>(&t);
}

static __device__ __forceinline__ uint32_t packh2(__half a, __half b)
{
    __half2 t(a, b);
    return *reinterpret_cast<uint32_t*>(&t);
}

// ---------------------------------------------------------------------------
// Build Dt (D^T) and Dm (D) as bf16 hi/lo (verified round 4)
// ---------------------------------------------------------------------------
__global__ void build_D_kernel()
{
    int idx = blockIdx.x * blockDim.x + threadIdx.x;
    int r = idx >> 11;
    int c = idx & (DIMN - 1);
    const float n0 = 0.022097086912079612f;  // sqrt(1/2048)
    const float n1 = 0.03125f;               // sqrt(2/2048)

    int q1 = ((2 * r + 1) * c) & 8191;
    float v1 = cospif((float)q1 * (1.0f / 4096.0f)) * ((c == 0) ? n0 : n1);
    bsplit(v1, g_Dt_hi[idx], g_Dt_lo[idx]);

    int q2 = ((2 * c + 1) * r) & 8191;
    float v2 = cospif((float)q2 * (1.0f / 4096.0f)) * ((r == 0) ? n0 : n1);
    bsplit(v2, g_Dm_hi[idx], g_Dm_lo[idx]);
}

// ---------------------------------------------------------------------------
// Converts (verified rounds 7/9)
// ---------------------------------------------------------------------------
__global__ void convert_split(const float* __restrict__ s,
                              __nv_bfloat16* __restrict__ hi,
                              __nv_bfloat16* __restrict__ lo, int n)
{
    int i = (blockIdx.x * blockDim.x + threadIdx.x) << 3;
    if (i >= n) return;
    float4 v0 = *(const float4*)(s + i);
    float4 v1 = *(const float4*)(s + i + 4);
    __nv_bfloat16 h0, h1, h2, h3, h4, h5, h6, h7;
    __nv_bfloat16 l0, l1, l2, l3, l4, l5, l6, l7;
    bsplit(v0.x, h0, l0); bsplit(v0.y, h1, l1);
    bsplit(v0.z, h2, l2); bsplit(v0.w, h3, l3);
    bsplit(v1.x, h4, l4); bsplit(v1.y, h5, l5);
    bsplit(v1.z, h6, l6); bsplit(v1.w, h7, l7);
    uint4 hbuf, lbuf;
    hbuf.x = packbf(h0, h1); hbuf.y = packbf(h2, h3);
    hbuf.z = packbf(h4, h5); hbuf.w = packbf(h6, h7);
    lbuf.x = packbf(l0, l1); lbuf.y = packbf(l2, l3);
    lbuf.z = packbf(l4, l5); lbuf.w = packbf(l6, l7);
    *(uint4*)(hi + i) = hbuf;
    *(uint4*)(lo + i) = lbuf;
}

__global__ void convert_f16(const float* __restrict__ s,
                            __half* __restrict__ d, int n)
{
    int i = (blockIdx.x * blockDim.x + threadIdx.x) << 3;
    if (i >= n) return;
    float4 v0 = *(const float4*)(s + i);
    float4 v1 = *(const float4*)(s + i + 4);
    uint4 buf;
    buf.x = packh(v0.x, v0.y); buf.y = packh(v0.z, v0.w);
    buf.z = packh(v1.x, v1.y); buf.w = packh(v1.z, v1.w);
    *(uint4*)(d + i) = buf;
}

__global__ void convert_split_f16(const float* __restrict__ s,
                                  __half* __restrict__ hi,
                                  __half* __restrict__ lo, int n)
{
    int i = (blockIdx.x * blockDim.x + threadIdx.x) << 3;
    if (i >= n) return;
    float4 v0 = *(const float4*)(s + i);
    float4 v1 = *(const float4*)(s + i + 4);
    __half h0, h1, h2, h3, h4, h5, h6, h7;
    __half l0, l1, l2, l3, l4, l5, l6, l7;
    hsplit(v0.x, h0, l0); hsplit(v0.y, h1, l1);
    hsplit(v0.z, h2, l2); hsplit(v0.w, h3, l3);
    hsplit(v1.x, h4, l4); hsplit(v1.y, h5, l5);
    hsplit(v1.z, h6, l6); hsplit(v1.w, h7, l7);
    uint4 hbuf, lbuf;
    hbuf.x = packh2(h0, h1); hbuf.y = packh2(h2, h3);
    hbuf.z = packh2(h4, h5); hbuf.w = packh2(h6, h7);
    lbuf.x = packh2(l0, l1); lbuf.y = packh2(l2, l3);
    lbuf.z = packh2(l4, l5); lbuf.w = packh2(l6, l7);
    *(uint4*)(hi + i) = hbuf;
    *(uint4*)(lo + i) = lbuf;
}

__global__ void reduce4_split(const float* __restrict__ part,
                              const float* __restrict__ colscale,
                              __nv_bfloat16* __restrict__ hi,
                              __nv_bfloat16* __restrict__ lo,
                              int n, int N)
{
    int i = (blockIdx.x * blockDim.x + threadIdx.x) << 2;
    if (i >= n) return;
    float4 a = *(const float4*)(part + i);
    float4 b = *(const float4*)(part + (size_t)n + i);
    float4 c = *(const float4*)(part + 2 * (size_t)n + i);
    float4 d = *(const float4*)(part + 3 * (size_t)n + i);
    float v0 = (a.x + b.x) + (c.x + d.x);
    float v1 = (a.y + b.y) + (c.y + d.y);
    float v2 = (a.z + b.z) + (c.z + d.z);
    float v3 = (a.w + b.w) + (c.w + d.w);
    if (colscale) {
        int col = i & (N - 1);
        v0 *= colscale[col];     v1 *= colscale[col + 1];
        v2 *= colscale[col + 2]; v3 *= colscale[col + 3];
    }
    __nv_bfloat16 h0, h1, h2, h3, l0, l1, l2, l3;
    bsplit(v0, h0, l0); bsplit(v1, h1, l1);
    bsplit(v2, h2, l2); bsplit(v3, h3, l3);
    __nv_bfloat162 hp0(h0, h1), hp1(h2, h3), lp0(l0, l1), lp1(l2, l3);
    *(__nv_bfloat162*)(hi + i)     = hp0;
    *(__nv_bfloat162*)(hi + i + 2) = hp1;
    *(__nv_bfloat162*)(lo + i)     = lp0;
    *(__nv_bfloat162*)(lo + i + 2) = lp1;
}

__global__ void reduce4_split_f16(const float* __restrict__ part,
                                  __half* __restrict__ hi,
                                  __half* __restrict__ lo, int n)
{
    int i = (blockIdx.x * blockDim.x + threadIdx.x) << 2;
    if (i >= n) return;
    float4 a = *(const float4*)(part + i);
    float4 b = *(const float4*)(part + (size_t)n + i);
    float4 c = *(const float4*)(part + 2 * (size_t)n + i);
    float4 d = *(const float4*)(part + 3 * (size_t)n + i);
    float v0 = (a.x + b.x) + (c.x + d.x);
    float v1 = (a.y + b.y) + (c.y + d.y);
    float v2 = (a.z + b.z) + (c.z + d.z);
    float v3 = (a.w + b.w) + (c.w + d.w);
    __half h0, h1, h2, h3, l0, l1, l2, l3;
    hsplit(v0, h0, l0); hsplit(v1, h1, l1);
    hsplit(v2, h2, l2); hsplit(v3, h3, l3);
    uint2 hb, lb;
    hb.x = packh2(h0, h1); hb.y = packh2(h2, h3);
    lb.x = packh2(l0, l1); lb.y = packh2(l2, l3);
    *(uint2*)(hi + i) = hb;
    *(uint2*)(lo + i) = lb;
}

__global__ void merge_bias(const float* __restrict__ bmu, const float* __restrict__ blv)
{
    int i = blockIdx.x * blockDim.x + threadIdx.x;
    if (i < 256)      g_bml[i] = bmu[i];
    else if (i < 512) g_bml[i] = blv[i - 256];
}

// ---------------------------------------------------------------------------
// mma.sync / ldmatrix / cp.async helpers
// ---------------------------------------------------------------------------
#define LDSM4(r0, r1, r2, r3, addr)                                            \
    asm volatile("ldmatrix.sync.aligned.m8n8.x4.shared.b16 {%0,%1,%2,%3}, [%4];" \
                 : "=r"(r0), "=r"(r1), "=r"(r2), "=r"(r3) : "r"(addr))

#define MMA_BF16(c, a, b)                                                      \
    asm volatile("mma.sync.aligned.m16n8k16.row.col.f32.bf16.bf16.f32 "        \
                 "{%0,%1,%2,%3},{%4,%5,%6,%7},{%8,%9},{%0,%1,%2,%3};"          \
                 : "+f"((c)[0]), "+f"((c)[1]), "+f"((c)[2]), "+f"((c)[3])      \
                 : "r"((a)[0]), "r"((a)[1]), "r"((a)[2]), "r"((a)[3]),         \
                   "r"((b)[0]), "r"((b)[1]))

#define MMA_F16(c, a, b)                                                       \
    asm volatile("mma.sync.aligned.m16n8k16.row.col.f32.f16.f16.f32 "          \
                 "{%0,%1,%2,%3},{%4,%5,%6,%7},{%8,%9},{%0,%1,%2,%3};"          \
                 : "+f"((c)[0]), "+f"((c)[1]), "+f"((c)[2]), "+f"((c)[3])      \
                 : "r"((a)[0]), "r"((a)[1]), "r"((a)[2]), "r"((a)[3]),         \
                   "r"((b)[0]), "r"((b)[1]))

#define CP16(sa, ga)                                                           \
    asm volatile("cp.async.cg.shared.global [%0], [%1], 16;"                   \
                 :: "r"(sa), "l"(ga) : "memory")
#define CP_COMMIT() asm volatile("cp.async.commit_group;" ::: "memory")
#define CP_WAIT(nn)  asm volatile("cp.async.wait_group %0;" :: "n"(nn) : "memory")

// ---------------------------------------------------------------------------
// bf16x3 tensor-core NT GEMM (weight prep; verified rounds 5-9), split-K.
// ---------------------------------------------------------------------------
__global__ __launch_bounds__(256, 1)
void gemm_bf16x3(const __nv_bfloat16* __restrict__ Ahp,
                 const __nv_bfloat16* __restrict__ Alp,
                 const __nv_bfloat16* __restrict__ Bhp,
                 const __nv_bfloat16* __restrict__ Blp,
                 float* __restrict__ Cpart,
                 int M, int N, int K, int klen)
{
    extern __shared__ __align__(1024) char smem[];
    const uint32_t sb = (uint32_t)__cvta_generic_to_shared(smem);

    const int tid   = threadIdx.x;
    const int lane  = tid & 31;
    const int wid   = tid >> 5;
    const int warpm = wid & 3;
    const int warpn = wid >> 2;
    const int bm = blockIdx.y * BM;
    const int bn = blockIdx.x * BN;
    const int kbase = blockIdx.z * klen;

    const uint32_t aOff = (uint32_t)(warpm * 32 + (lane & 15)) * ROWB
                        + (uint32_t)(lane >> 4) * 16u;
    const uint32_t bOff = (uint32_t)(warpn * 64 + (lane & 7) + ((lane & 16) ? 8 : 0)) * ROWB
                        + (uint32_t)((lane >> 3) & 1) * 16u;

    float acc[2][8][4];
    #pragma unroll
    for (int i = 0; i < 2; i++)
        #pragma unroll
        for (int j = 0; j < 8; j++)
            #pragma unroll
            for (int q = 0; q < 4; q++) acc[i][j][q] = 0.0f;

    const int nk = klen >> 6;

    auto issue_stage = [&](int kt) {
        const uint32_t base = sb + (uint32_t)(kt % NST) * STAGEB;
        const size_t kof = (size_t)kbase + (size_t)kt * BK;
        #pragma unroll
        for (int h = 0; h < 4; h++) {
            const int c   = tid + h * 256;
            const int row = c >> 3;
            const int q   = c & 7;
            const uint32_t so = (uint32_t)row * ROWB + (uint32_t)q * 16u;
            const size_t ga = (size_t)(bm + row) * K + kof + (size_t)q * 8;
            const size_t gb = (size_t)(bn + row) * K + kof + (size_t)q * 8;
            CP16(base + so,               Ahp + ga);
            CP16(base + TILEB + so,       Alp + ga);
            CP16(base + 2u * TILEB + so,  Bhp + gb);
            CP16(base + 3u * TILEB + so,  Blp + gb);
        }
    };

    auto load_frags = [&](uint32_t base, uint32_t kb, uint32_t* F) {
        const uint32_t aHi = base,              aLo = base + TILEB;
        const uint32_t bHi = base + 2u * TILEB, bLo = base + 3u * TILEB;
        #pragma unroll
        for (int mf = 0; mf < 2; mf++) {
            uint32_t ad = aHi + aOff + (uint32_t)mf * (16u * ROWB) + kb;
            LDSM4(F[mf*4+0], F[mf*4+1], F[mf*4+2], F[mf*4+3], ad);
            uint32_t al = aLo + aOff + (uint32_t)mf * (16u * ROWB) + kb;
            LDSM4(F[8+mf*4+0], F[8+mf*4+1], F[8+mf*4+2], F[8+mf*4+3], al);
        }
        #pragma unroll
        for (int bf = 0; bf < 4; bf++) {
            uint32_t bd = bHi + bOff + (uint32_t)bf * (16u * ROWB) + kb;
            LDSM4(F[16+bf*4+0], F[16+bf*4+1], F[16+bf*4+2], F[16+bf*4+3], bd);
            uint32_t bl = bLo + bOff + (uint32_t)bf * (16u * ROWB) + kb;
            LDSM4(F[32+bf*4+0], F[32+bf*4+1], F[32+bf*4+2], F[32+bf*4+3], bl);
        }
    };

    auto mma_step = [&](const uint32_t* F) {
        #pragma unroll
        for (int mf = 0; mf < 2; mf++)
            #pragma unroll
            for (int nf = 0; nf < 8; nf++) {
                const uint32_t* BhF = &F[16 + (nf >> 1) * 4];
                uint32_t bh[2] = { BhF[(nf & 1) ? 2 : 0], BhF[(nf & 1) ? 3 : 1] };
                MMA_BF16(acc[mf][nf], &F[mf * 4], bh);        // hi*hi
            }
        #pragma unroll
        for (int mf = 0; mf < 2; mf++)
            #pragma unroll
            for (int nf = 0; nf < 8; nf++) {
                const uint32_t* BlF = &F[32 + (nf >> 1) * 4];
                uint32_t bl2[2] = { BlF[(nf & 1) ? 2 : 0], BlF[(nf & 1) ? 3 : 1] };
                MMA_BF16(acc[mf][nf], &F[mf * 4], bl2);       // hi*lo
            }
        #pragma unroll
        for (int mf = 0; mf < 2; mf++)
            #pragma unroll
            for (int nf = 0; nf < 8; nf++) {
                const uint32_t* BhF = &F[16 + (nf >> 1) * 4];
                uint32_t bh[2] = { BhF[(nf & 1) ? 2 : 0], BhF[(nf & 1) ? 3 : 1] };
                MMA_BF16(acc[mf][nf], &F[8 + mf * 4], bh);    // lo*hi
            }
    };

    #pragma unroll
    for (int s = 0; s < NST - 1; s++) { issue_stage(s); CP_COMMIT(); }

    uint32_t Fr[2][48];

    for (int kt = 0; kt < nk; kt++) {
        CP_WAIT(NST - 2);
        __syncthreads();
        const uint32_t base = sb + (uint32_t)(kt % NST) * STAGEB;
        load_frags(base, 0u, Fr[0]);
        if (kt + NST - 1 < nk) issue_stage(kt + NST - 1);
        CP_COMMIT();
        #pragma unroll
        for (int ks = 0; ks < 4; ks++) {
            if (ks < 3)
                load_frags(base, (uint32_t)(ks + 1) * 32u, Fr[(ks + 1) & 1]);
            mma_step(Fr[ks & 1]);
        }
    }

    // fp32 split-K partial epilogue
    const int g  = lane >> 2;
    const int tg = lane & 3;
    float* base2 = Cpart + (size_t)blockIdx.z * ((size_t)M * N);
    #pragma unroll
    for (int mf = 0; mf < 2; mf++) {
        const int r0 = bm + warpm * 32 + mf * 16 + g;
        #pragma unroll
        for (int nf = 0; nf < 8; nf++) {
            const int col = bn + warpn * 64 + nf * 8 + tg * 2;
            *(float2*)(base2 + (size_t)r0 * N + col) =
                make_float2(acc[mf][nf][0], acc[mf][nf][1]);
            *(float2*)(base2 + (size_t)(r0 + 8) * N + col) =
                make_float2(acc[mf][nf][2], acc[mf][nf][3]);
        }
    }
}

// ---------------------------------------------------------------------------
// f16x2 activation GEMM v2: 128x64 CTA tile, 2 CTAs/SM (occupancy experiment).
// C[m][n] = sum_k A[m][k]*(Bh+Bl)[n][k]  (2 MMAs/acc)
// 8 warps as 4m x 2n, warp tile 32x32, single-buffered fragments.
// ---------------------------------------------------------------------------
__global__ __launch_bounds__(256, 2)
void gemm_f16x2(const __half* __restrict__ Ap,
                const __half* __restrict__ Bhp,
                const __half* __restrict__ Blp,
                const float* __restrict__ bias,
                __half* __restrict__ Cs,
                float* __restrict__ Cf,
                int M, int N, int K, int do_relu)
{
    extern __shared__ __align__(1024) char smem[];
    const uint32_t sb = (uint32_t)__cvta_generic_to_shared(smem);

    const int tid   = threadIdx.x;
    const int lane  = tid & 31;
    const int wid   = tid >> 5;
    const int warpm = wid & 3;            // 4 warps over M (32 rows each)
    const int warpn = wid >> 2;           // 2 warps over N (32 cols each)
    const int bm = blockIdx.y * 128;
    const int bn = blockIdx.x * 64;

    const uint32_t aOff = (uint32_t)(warpm * 32 + (lane & 15)) * ROWB
                        + (uint32_t)(lane >> 4) * 16u;
    const uint32_t bOff = (uint32_t)(warpn * 32 + (lane & 7) + ((lane & 16) ? 8 : 0)) * ROWB
                        + (uint32_t)((lane >> 3) & 1) * 16u;

    float acc[2][4][4];
    #pragma unroll
    for (int i = 0; i < 2; i++)
        #pragma unroll
        for (int j = 0; j < 4; j++)
            #pragma unroll
            for (int q = 0; q < 4; q++) acc[i][j][q] = 0.0f;

    const int nk = K >> 6;

    // 2048 16B chunks per stage: A 1024 (rows 0..127), Bh 512, Bl 512
    auto issue_stage = [&](int kt) {
        const uint32_t base = sb + (uint32_t)(kt % NST2) * STAGEB2;
        const size_t kof = (size_t)kt * BK;
        #pragma unroll
        for (int h = 0; h < 4; h++) {     // A chunks
            const int c   = tid + h * 256;
            const int row = c >> 3;
            const int q   = c & 7;
            const uint32_t so = (uint32_t)row * ROWB + (uint32_t)q * 16u;
            CP16(base + so, Ap + (size_t)(bm + row) * K + kof + (size_t)q * 8);
        }
        #pragma unroll
        for (int h = 0; h < 2; h++) {     // Bh chunks (rows 0..63)
            const int c   = tid + h * 256;
            const int row = c >> 3;
            const int q   = c & 7;
            const uint32_t so = (uint32_t)row * ROWB + (uint32_t)q * 16u;
            const size_t gb = (size_t)(bn + row) * K + kof + (size_t)q * 8;
            CP16(base + TILEB_A + so,             Bhp + gb);
            CP16(base + TILEB_A + TILEB_B + so,   Blp + gb);
        }
    };

    // F[0..7]=A(mf0,mf1), F[8..15]=Bh(bf0,bf1), F[16..23]=Bl
    auto load_frags = [&](uint32_t base, uint32_t kb, uint32_t* F) {
        const uint32_t bHi = base + TILEB_A, bLo = base + TILEB_A + TILEB_B;
        #pragma unroll
        for (int mf = 0; mf < 2; mf++) {
            uint32_t ad = base + aOff + (uint32_t)mf * (16u * ROWB) + kb;
            LDSM4(F[mf*4+0], F[mf*4+1], F[mf*4+2], F[mf*4+3], ad);
        }
        #pragma unroll
        for (int bf = 0; bf < 2; bf++) {
            uint32_t bd = bHi + bOff + (uint32_t)bf * (16u * ROWB) + kb;
            LDSM4(F[8+bf*4+0], F[8+bf*4+1], F[8+bf*4+2], F[8+bf*4+3], bd);
            uint32_t bl = bLo + bOff + (uint32_t)bf * (16u * ROWB) + kb;
            LDSM4(F[16+bf*4+0], F[16+bf*4+1], F[16+bf*4+2], F[16+bf*4+3], bl);
        }
    };

    auto mma_step = [&](const uint32_t* F) {
        #pragma unroll
        for (int mf = 0; mf < 2; mf++)
            #pragma unroll
            for (int nf = 0; nf < 4; nf++) {
                const uint32_t* BhF = &F[8 + (nf >> 1) * 4];
                uint32_t bh[2] = { BhF[(nf & 1) ? 2 : 0], BhF[(nf & 1) ? 3 : 1] };
                MMA_F16(acc[mf][nf], &F[mf * 4], bh);        // A*hi
            }
        #pragma unroll
        for (int mf = 0; mf < 2; mf++)
            #pragma unroll
            for (int nf = 0; nf < 4; nf++) {
                const uint32_t* BlF = &F[16 + (nf >> 1) * 4];
                uint32_t bl2[2] = { BlF[(nf & 1) ? 2 : 0], BlF[(nf & 1) ? 3 : 1] };
                MMA_F16(acc[mf][nf], &F[mf * 4], bl2);       // A*lo
            }
    };

    #pragma unroll
    for (int s = 0; s < NST2 - 1; s++) { issue_stage(s); CP_COMMIT(); }

    uint32_t F[24];

    for (int kt = 0; kt < nk; kt++) {
        CP_WAIT(NST2 - 2);
        __syncthreads();
        const uint32_t base = sb + (uint32_t)(kt % NST2) * STAGEB2;
        if (kt + NST2 - 1 < nk) issue_stage(kt + NST2 - 1);
        CP_COMMIT();
        #pragma unroll
        for (int ks = 0; ks < 4; ks++) {
            load_frags(base, (uint32_t)ks * 32u, F);
            mma_step(F);
        }
    }

    // ---- epilogue ----
    const int g  = lane >> 2;
    const int tg = lane & 3;
    #pragma unroll
    for (int mf = 0; mf < 2; mf++) {
        const int r0 = bm + warpm * 32 + mf * 16 + g;
        #pragma unroll
        for (int nf = 0; nf < 4; nf++) {
            const int col = bn + warpn * 32 + nf * 8 + tg * 2;
            float b0 = bias[col], b1 = bias[col + 1];
            float v0 = acc[mf][nf][0] + b0, v1 = acc[mf][nf][1] + b1;
            float v2 = acc[mf][nf][2] + b0, v3 = acc[mf][nf][3] + b1;
            if (do_relu) {
                v0 = fmaxf(v0, 0.0f); v1 = fmaxf(v1, 0.0f);
                v2 = fmaxf(v2, 0.0f); v3 = fmaxf(v3, 0.0f);
            }
            if (Cf) {      // final: N==512; cols [0,256) mu, [256,512) logvar
                float* p0;
                float* p1;
                if (col < 256) {
                    p0 = Cf + (size_t)r0 * 256 + col;
                    p1 = Cf + (size_t)(r0 + 8) * 256 + col;
                } else {
                    float* half2p = Cf + (size_t)BATCH * 256;
                    p0 = half2p + (size_t)r0 * 256 + (col - 256);
                    p1 = half2p + (size_t)(r0 + 8) * 256 + (col - 256);
                }
                *(float2*)p0 = make_float2(v0, v1);
                *(float2*)p1 = make_float2(v2, v3);
            } else {
                *(uint32_t*)(Cs + (size_t)r0 * N + col)       = packh(v0, v1);
                *(uint32_t*)(Cs + (size_t)(r0 + 8) * N + col) = packh(v2, v3);
            }
        }
    }
}

// ---------------------------------------------------------------------------
// Launch
// ---------------------------------------------------------------------------
extern "C" void kernel_launch(void* const* d_in, const int* in_sizes, int n_in,
                              void* d_out, int out_size)
{
    const float* x   = (const float*)d_in[0];
    const float* fw  = (const float*)d_in[1];
    const float* kp  = (const float*)d_in[2];
    const float* W1  = (const float*)d_in[3];
    const float* b1  = (const float*)d_in[4];
    const float* W2  = (const float*)d_in[5];
    const float* b2  = (const float*)d_in[6];
    const float* Wmu = (const float*)d_in[7];
    const float* bmu = (const float*)d_in[8];
    const float* Wlv = (const float*)d_in[9];
    const float* blv = (const float*)d_in[10];
    float* out = (float*)d_out;

    __nv_bfloat16 *Dt_h, *Dt_l, *Dm_h, *Dm_l, *W1_h, *W1_l, *A1_h, *A1_l;
    __half *x16, *h1_16, *h2_16, *W1ef_h, *W1ef_l, *W2f_h, *W2f_l, *Wmlf_h, *Wmlf_l;
    float *bml, *bscale, *part;
    cudaGetSymbolAddress((void**)&Dt_h,   g_Dt_hi);  cudaGetSymbolAddress((void**)&Dt_l,  g_Dt_lo);
    cudaGetSymbolAddress((void**)&Dm_h,   g_Dm_hi);  cudaGetSymbolAddress((void**)&Dm_l,  g_Dm_lo);
    cudaGetSymbolAddress((void**)&W1_h,   g_W1_hi);  cudaGetSymbolAddress((void**)&W1_l,  g_W1_lo);
    cudaGetSymbolAddress((void**)&A1_h,   g_A1_hi);  cudaGetSymbolAddress((void**)&A1_l,  g_A1_lo);
    cudaGetSymbolAddress((void**)&x16,    g_x16);
    cudaGetSymbolAddress((void**)&h1_16,  g_h1_16);
    cudaGetSymbolAddress((void**)&h2_16,  g_h2_16);
    cudaGetSymbolAddress((void**)&W1ef_h, g_W1ef_hi); cudaGetSymbolAddress((void**)&W1ef_l, g_W1ef_lo);
    cudaGetSymbolAddress((void**)&W2f_h,  g_W2f_hi);  cudaGetSymbolAddress((void**)&W2f_l,  g_W2f_lo);
    cudaGetSymbolAddress((void**)&Wmlf_h, g_Wmlf_hi); cudaGetSymbolAddress((void**)&Wmlf_l, g_Wmlf_lo);
    cudaGetSymbolAddress((void**)&bml,    g_bml);
    cudaGetSymbolAddress((void**)&bscale, g_bscale);
    cudaGetSymbolAddress((void**)&part,   g_part);

    cudaFuncSetAttribute(gemm_bf16x3,
                         cudaFuncAttributeMaxDynamicSharedMemorySize, SMEM_GEMM);
    cudaFuncSetAttribute(gemm_f16x2,
                         cudaFuncAttributeMaxDynamicSharedMemorySize, SMEM_GEMM2);

    build_scale_kernel<<<8, 256>>>(fw, kp);
    build_D_kernel<<<(DIMN * DIMN) / 256, 256>>>();

    convert_f16<<<(BATCH * DIMN / 8 + 255) / 256, 256>>>(x, x16, BATCH * DIMN);
    convert_split<<<(1024 * DIMN / 8 + 255) / 256, 256>>>(W1, W1_h, W1_l, 1024 * DIMN);
    convert_split_f16<<<(512 * 1024 / 8 + 255) / 256, 256>>>(W2, W2f_h, W2f_l, 512 * 1024);
    convert_split_f16<<<(256 * 512 / 8 + 255) / 256, 256>>>(Wmu, Wmlf_h, Wmlf_l, 256 * 512);
    convert_split_f16<<<(256 * 512 / 8 + 255) / 256, 256>>>(Wlv, Wmlf_h + 256 * 512,
                                                            Wmlf_l + 256 * 512, 256 * 512);
    merge_bias<<<2, 256>>>(bmu, blv);

    const int nW = 1024 * DIMN;

    // A1[j][kf] = (sum_n W1[j][n] * D[kf][n]) * bscale[kf]   (split-K=4, bf16x3)
    gemm_bf16x3<<<dim3(16, 8, 4), 256, SMEM_GEMM>>>(
        W1_h, W1_l, Dm_h, Dm_l, part, 1024, 2048, 2048, 512);
    reduce4_split<<<(nW / 4 + 255) / 256, 256>>>(part, bscale, A1_h, A1_l, nW, 2048);

    // W1e[j][m] = sum_kf A1[j][kf] * Dt[m][kf]               (split-K=4, bf16x3)
    gemm_bf16x3<<<dim3(16, 8, 4), 256, SMEM_GEMM>>>(
        A1_h, A1_l, Dt_h, Dt_l, part, 1024, 2048, 2048, 512);
    reduce4_split_f16<<<(nW / 4 + 255) / 256, 256>>>(part, W1ef_h, W1ef_l, nW);

    // h1 = relu(x @ W1e^T + b1)        (fp16 A x fp16x2 B, 2 MMAs, 2 CTA/SM)
    gemm_f16x2<<<dim3(16, 128), 256, SMEM_GEMM2>>>(
        x16, W1ef_h, W1ef_l, b1, h1_16, nullptr, BATCH, 1024, 2048, 1);
    // h2 = relu(h1 @ W2^T + b2)
    gemm_f16x2<<<dim3(8, 128), 256, SMEM_GEMM2>>>(
        h1_16, W2f_h, W2f_l, b2, h2_16, nullptr, BATCH, 512, 1024, 1);
    // [mu | logvar] = h2 @ [Wmu;Wlv]^T + [bmu;blv]
    gemm_f16x2<<<dim3(8, 128), 256, SMEM_GEMM2>>>(
        h2_16, Wmlf_h, Wmlf_l, bml, nullptr, out, BATCH, 512, 512, 0);
}

// round 11
// speedup vs baseline: 1.9998x; 1.4293x over previous
#include <cuda_runtime.h>
#include <cuda_bf16.h>
#include <cuda_fp16.h>
#include <math.h>
#include <stdint.h>

// Problem constants
#define DIMN  2048
#define BATCH 16384

// Shared tile constants
#define BK    64
#define ROWB  144u                    // 128B data + 16B pad -> conflict-free LDSM

// bf16x3 weight GEMM (verified R5-R10): 128x128 tile, 4 tiles/stage, 3 stages
#define BM    128
#define BN    128
#define TILEB (128u * ROWB)           // 18432 B per 128x64 16-bit tile
#define NST   3
#define STAGEB (4u * TILEB)
#define SMEM_GEMM (NST * STAGEB)      // 221184 B

// pure-fp16 activation GEMM: 128x128 tile, A+B single, 3 stages, 2 CTAs/SM
#define NST2     3
#define STAGEB2  (2u * TILEB)         // 36864
#define SMEM_GEMM2 (NST2 * STAGEB2)   // 110592 B

// ---------------------------------------------------------------------------
// Device scratch (static — no runtime allocs)
// ---------------------------------------------------------------------------
__device__ __align__(128) __nv_bfloat16 g_Dt_hi [DIMN * DIMN];
__device__ __align__(128) __nv_bfloat16 g_Dt_lo [DIMN * DIMN];
__device__ __align__(128) __nv_bfloat16 g_Dm_hi [DIMN * DIMN];
__device__ __align__(128) __nv_bfloat16 g_Dm_lo [DIMN * DIMN];
__device__ __align__(128) __nv_bfloat16 g_W1_hi [1024 * DIMN];
__device__ __align__(128) __nv_bfloat16 g_W1_lo [1024 * DIMN];
__device__ __align__(128) __nv_bfloat16 g_A1_hi [1024 * DIMN];
__device__ __align__(128) __nv_bfloat16 g_A1_lo [1024 * DIMN];
__device__ __align__(128) float g_part[4 * 1024 * DIMN];   // split-K partials
// fp16 activation-path arrays (all single-term now)
__device__ __align__(128) __half g_x16   [BATCH * DIMN];
__device__ __align__(128) __half g_h1_16 [BATCH * 1024];
__device__ __align__(128) __half g_h2_16 [BATCH * 512];
__device__ __align__(128) __half g_W1ef  [1024 * DIMN];
__device__ __align__(128) __half g_W2f   [512 * 1024];
__device__ __align__(128) __half g_Wmlf  [512 * 512];
__device__ float g_bml[512];
__device__ float g_bscale[DIMN];

// ---------------------------------------------------------------------------
// Band-scale (verified round 1)
// ---------------------------------------------------------------------------
__global__ void build_scale_kernel(const float* __restrict__ fw,
                                   const float* __restrict__ kptr)
{
    int idx = blockIdx.x * blockDim.x + threadIdx.x;
    if (idx >= DIMN) return;
    const float kv = *kptr;
    float val = 1.0f;
    const double step = 2047.0 / 30.0;
    #pragma unroll 1
    for (int i = 0; i < 30; i++) {
        int s = (int)(step * (double)i);
        int e = (i == 29) ? 2047 : (int)(step * (double)(i + 1));
        if (idx >= s && idx < e) {
            float f;
            if (e <= 30) f = 1.0f + fw[i] * kv * (1.0f - (float)i / 30.0f);
            else         f = 1.0f - fw[i] * kv * (1.0f - (float)(i - 30) / 30.0f);
            val = f;
        }
    }
    g_bscale[idx] = val;
}

static __device__ __forceinline__ void bsplit(float v, __nv_bfloat16& h, __nv_bfloat16& l)
{
    h = __float2bfloat16_rn(v);
    l = __float2bfloat16_rn(v - __bfloat162float(h));
}

static __device__ __forceinline__ uint32_t packbf(__nv_bfloat16 a, __nv_bfloat16 b)
{
    __nv_bfloat162 t(a, b);
    return *reinterpret_cast<uint32_t*>(&t);
}

static __device__ __forceinline__ uint32_t packh(float a, float b)
{
    __half2 t = __floats2half2_rn(a, b);
    return *reinterpret_cast<uint32_t*>(&t);
}

// ---------------------------------------------------------------------------
// Build Dt (D^T) and Dm (D) as bf16 hi/lo (verified round 4)
// ---------------------------------------------------------------------------
__global__ void build_D_kernel()
{
    int idx = blockIdx.x * blockDim.x + threadIdx.x;
    int r = idx >> 11;
    int c = idx & (DIMN - 1);
    const float n0 = 0.022097086912079612f;  // sqrt(1/2048)
    const float n1 = 0.03125f;               // sqrt(2/2048)

    int q1 = ((2 * r + 1) * c) & 8191;
    float v1 = cospif((float)q1 * (1.0f / 4096.0f)) * ((c == 0) ? n0 : n1);
    bsplit(v1, g_Dt_hi[idx], g_Dt_lo[idx]);

    int q2 = ((2 * c + 1) * r) & 8191;
    float v2 = cospif((float)q2 * (1.0f / 4096.0f)) * ((r == 0) ? n0 : n1);
    bsplit(v2, g_Dm_hi[idx], g_Dm_lo[idx]);
}

// ---------------------------------------------------------------------------
// Converts
// ---------------------------------------------------------------------------
__global__ void convert_split(const float* __restrict__ s,
                              __nv_bfloat16* __restrict__ hi,
                              __nv_bfloat16* __restrict__ lo, int n)
{
    int i = (blockIdx.x * blockDim.x + threadIdx.x) << 3;
    if (i >= n) return;
    float4 v0 = *(const float4*)(s + i);
    float4 v1 = *(const float4*)(s + i + 4);
    __nv_bfloat16 h0, h1, h2, h3, h4, h5, h6, h7;
    __nv_bfloat16 l0, l1, l2, l3, l4, l5, l6, l7;
    bsplit(v0.x, h0, l0); bsplit(v0.y, h1, l1);
    bsplit(v0.z, h2, l2); bsplit(v0.w, h3, l3);
    bsplit(v1.x, h4, l4); bsplit(v1.y, h5, l5);
    bsplit(v1.z, h6, l6); bsplit(v1.w, h7, l7);
    uint4 hbuf, lbuf;
    hbuf.x = packbf(h0, h1); hbuf.y = packbf(h2, h3);
    hbuf.z = packbf(h4, h5); hbuf.w = packbf(h6, h7);
    lbuf.x = packbf(l0, l1); lbuf.y = packbf(l2, l3);
    lbuf.z = packbf(l4, l5); lbuf.w = packbf(l6, l7);
    *(uint4*)(hi + i) = hbuf;
    *(uint4*)(lo + i) = lbuf;
}

__global__ void convert_f16(const float* __restrict__ s,
                            __half* __restrict__ d, int n)
{
    int i = (blockIdx.x * blockDim.x + threadIdx.x) << 3;
    if (i >= n) return;
    float4 v0 = *(const float4*)(s + i);
    float4 v1 = *(const float4*)(s + i + 4);
    uint4 buf;
    buf.x = packh(v0.x, v0.y); buf.y = packh(v0.z, v0.w);
    buf.z = packh(v1.x, v1.y); buf.w = packh(v1.z, v1.w);
    *(uint4*)(d + i) = buf;
}

__global__ void reduce4_split(const float* __restrict__ part,
                              const float* __restrict__ colscale,
                              __nv_bfloat16* __restrict__ hi,
                              __nv_bfloat16* __restrict__ lo,
                              int n, int N)
{
    int i = (blockIdx.x * blockDim.x + threadIdx.x) << 2;
    if (i >= n) return;
    float4 a = *(const float4*)(part + i);
    float4 b = *(const float4*)(part + (size_t)n + i);
    float4 c = *(const float4*)(part + 2 * (size_t)n + i);
    float4 d = *(const float4*)(part + 3 * (size_t)n + i);
    float v0 = (a.x + b.x) + (c.x + d.x);
    float v1 = (a.y + b.y) + (c.y + d.y);
    float v2 = (a.z + b.z) + (c.z + d.z);
    float v3 = (a.w + b.w) + (c.w + d.w);
    if (colscale) {
        int col = i & (N - 1);
        v0 *= colscale[col];     v1 *= colscale[col + 1];
        v2 *= colscale[col + 2]; v3 *= colscale[col + 3];
    }
    __nv_bfloat16 h0, h1, h2, h3, l0, l1, l2, l3;
    bsplit(v0, h0, l0); bsplit(v1, h1, l1);
    bsplit(v2, h2, l2); bsplit(v3, h3, l3);
    __nv_bfloat162 hp0(h0, h1), hp1(h2, h3), lp0(l0, l1), lp1(l2, l3);
    *(__nv_bfloat162*)(hi + i)     = hp0;
    *(__nv_bfloat162*)(hi + i + 2) = hp1;
    *(__nv_bfloat162*)(lo + i)     = lp0;
    *(__nv_bfloat162*)(lo + i + 2) = lp1;
}

// sum 4 split-K fp32 partials -> single fp16 (W1e)
__global__ void reduce4_f16(const float* __restrict__ part,
                            __half* __restrict__ dst, int n)
{
    int i = (blockIdx.x * blockDim.x + threadIdx.x) << 2;
    if (i >= n) return;
    float4 a = *(const float4*)(part + i);
    float4 b = *(const float4*)(part + (size_t)n + i);
    float4 c = *(const float4*)(part + 2 * (size_t)n + i);
    float4 d = *(const float4*)(part + 3 * (size_t)n + i);
    float v0 = (a.x + b.x) + (c.x + d.x);
    float v1 = (a.y + b.y) + (c.y + d.y);
    float v2 = (a.z + b.z) + (c.z + d.z);
    float v3 = (a.w + b.w) + (c.w + d.w);
    uint2 buf;
    buf.x = packh(v0, v1);
    buf.y = packh(v2, v3);
    *(uint2*)(dst + i) = buf;
}

__global__ void merge_bias(const float* __restrict__ bmu, const float* __restrict__ blv)
{
    int i = blockIdx.x * blockDim.x + threadIdx.x;
    if (i < 256)      g_bml[i] = bmu[i];
    else if (i < 512) g_bml[i] = blv[i - 256];
}

// ---------------------------------------------------------------------------
// mma.sync / ldmatrix / cp.async helpers
// ---------------------------------------------------------------------------
#define LDSM4(r0, r1, r2, r3, addr)                                            \
    asm volatile("ldmatrix.sync.aligned.m8n8.x4.shared.b16 {%0,%1,%2,%3}, [%4];" \
                 : "=r"(r0), "=r"(r1), "=r"(r2), "=r"(r3) : "r"(addr))

#define MMA_BF16(c, a, b)                                                      \
    asm volatile("mma.sync.aligned.m16n8k16.row.col.f32.bf16.bf16.f32 "        \
                 "{%0,%1,%2,%3},{%4,%5,%6,%7},{%8,%9},{%0,%1,%2,%3};"          \
                 : "+f"((c)[0]), "+f"((c)[1]), "+f"((c)[2]), "+f"((c)[3])      \
                 : "r"((a)[0]), "r"((a)[1]), "r"((a)[2]), "r"((a)[3]),         \
                   "r"((b)[0]), "r"((b)[1]))

#define MMA_F16(c, a, b)                                                       \
    asm volatile("mma.sync.aligned.m16n8k16.row.col.f32.f16.f16.f32 "          \
                 "{%0,%1,%2,%3},{%4,%5,%6,%7},{%8,%9},{%0,%1,%2,%3};"          \
                 : "+f"((c)[0]), "+f"((c)[1]), "+f"((c)[2]), "+f"((c)[3])      \
                 : "r"((a)[0]), "r"((a)[1]), "r"((a)[2]), "r"((a)[3]),         \
                   "r"((b)[0]), "r"((b)[1]))

#define CP16(sa, ga)                                                           \
    asm volatile("cp.async.cg.shared.global [%0], [%1], 16;"                   \
                 :: "r"(sa), "l"(ga) : "memory")
#define CP_COMMIT() asm volatile("cp.async.commit_group;" ::: "memory")
#define CP_WAIT(nn)  asm volatile("cp.async.wait_group %0;" :: "n"(nn) : "memory")

// ---------------------------------------------------------------------------
// bf16x3 tensor-core NT GEMM (weight prep; verified rounds 5-10), split-K.
// ---------------------------------------------------------------------------
__global__ __launch_bounds__(256, 1)
void gemm_bf16x3(const __nv_bfloat16* __restrict__ Ahp,
                 const __nv_bfloat16* __restrict__ Alp,
                 const __nv_bfloat16* __restrict__ Bhp,
                 const __nv_bfloat16* __restrict__ Blp,
                 float* __restrict__ Cpart,
                 int M, int N, int K, int klen)
{
    extern __shared__ __align__(1024) char smem[];
    const uint32_t sb = (uint32_t)__cvta_generic_to_shared(smem);

    const int tid   = threadIdx.x;
    const int lane  = tid & 31;
    const int wid   = tid >> 5;
    const int warpm = wid & 3;
    const int warpn = wid >> 2;
    const int bm = blockIdx.y * BM;
    const int bn = blockIdx.x * BN;
    const int kbase = blockIdx.z * klen;

    const uint32_t aOff = (uint32_t)(warpm * 32 + (lane & 15)) * ROWB
                        + (uint32_t)(lane >> 4) * 16u;
    const uint32_t bOff = (uint32_t)(warpn * 64 + (lane & 7) + ((lane & 16) ? 8 : 0)) * ROWB
                        + (uint32_t)((lane >> 3) & 1) * 16u;

    float acc[2][8][4];
    #pragma unroll
    for (int i = 0; i < 2; i++)
        #pragma unroll
        for (int j = 0; j < 8; j++)
            #pragma unroll
            for (int q = 0; q < 4; q++) acc[i][j][q] = 0.0f;

    const int nk = klen >> 6;

    auto issue_stage = [&](int kt) {
        const uint32_t base = sb + (uint32_t)(kt % NST) * STAGEB;
        const size_t kof = (size_t)kbase + (size_t)kt * BK;
        #pragma unroll
        for (int h = 0; h < 4; h++) {
            const int c   = tid + h * 256;
            const int row = c >> 3;
            const int q   = c & 7;
            const uint32_t so = (uint32_t)row * ROWB + (uint32_t)q * 16u;
            const size_t ga = (size_t)(bm + row) * K + kof + (size_t)q * 8;
            const size_t gb = (size_t)(bn + row) * K + kof + (size_t)q * 8;
            CP16(base + so,               Ahp + ga);
            CP16(base + TILEB + so,       Alp + ga);
            CP16(base + 2u * TILEB + so,  Bhp + gb);
            CP16(base + 3u * TILEB + so,  Blp + gb);
        }
    };

    auto load_frags = [&](uint32_t base, uint32_t kb, uint32_t* F) {
        const uint32_t aHi = base,              aLo = base + TILEB;
        const uint32_t bHi = base + 2u * TILEB, bLo = base + 3u * TILEB;
        #pragma unroll
        for (int mf = 0; mf < 2; mf++) {
            uint32_t ad = aHi + aOff + (uint32_t)mf * (16u * ROWB) + kb;
            LDSM4(F[mf*4+0], F[mf*4+1], F[mf*4+2], F[mf*4+3], ad);
            uint32_t al = aLo + aOff + (uint32_t)mf * (16u * ROWB) + kb;
            LDSM4(F[8+mf*4+0], F[8+mf*4+1], F[8+mf*4+2], F[8+mf*4+3], al);
        }
        #pragma unroll
        for (int bf = 0; bf < 4; bf++) {
            uint32_t bd = bHi + bOff + (uint32_t)bf * (16u * ROWB) + kb;
            LDSM4(F[16+bf*4+0], F[16+bf*4+1], F[16+bf*4+2], F[16+bf*4+3], bd);
            uint32_t bl = bLo + bOff + (uint32_t)bf * (16u * ROWB) + kb;
            LDSM4(F[32+bf*4+0], F[32+bf*4+1], F[32+bf*4+2], F[32+bf*4+3], bl);
        }
    };

    auto mma_step = [&](const uint32_t* F) {
        #pragma unroll
        for (int mf = 0; mf < 2; mf++)
            #pragma unroll
            for (int nf = 0; nf < 8; nf++) {
                const uint32_t* BhF = &F[16 + (nf >> 1) * 4];
                uint32_t bh[2] = { BhF[(nf & 1) ? 2 : 0], BhF[(nf & 1) ? 3 : 1] };
                MMA_BF16(acc[mf][nf], &F[mf * 4], bh);        // hi*hi
            }
        #pragma unroll
        for (int mf = 0; mf < 2; mf++)
            #pragma unroll
            for (int nf = 0; nf < 8; nf++) {
                const uint32_t* BlF = &F[32 + (nf >> 1) * 4];
                uint32_t bl2[2] = { BlF[(nf & 1) ? 2 : 0], BlF[(nf & 1) ? 3 : 1] };
                MMA_BF16(acc[mf][nf], &F[mf * 4], bl2);       // hi*lo
            }
        #pragma unroll
        for (int mf = 0; mf < 2; mf++)
            #pragma unroll
            for (int nf = 0; nf < 8; nf++) {
                const uint32_t* BhF = &F[16 + (nf >> 1) * 4];
                uint32_t bh[2] = { BhF[(nf & 1) ? 2 : 0], BhF[(nf & 1) ? 3 : 1] };
                MMA_BF16(acc[mf][nf], &F[8 + mf * 4], bh);    // lo*hi
            }
    };

    #pragma unroll
    for (int s = 0; s < NST - 1; s++) { issue_stage(s); CP_COMMIT(); }

    uint32_t Fr[2][48];

    for (int kt = 0; kt < nk; kt++) {
        CP_WAIT(NST - 2);
        __syncthreads();
        const uint32_t base = sb + (uint32_t)(kt % NST) * STAGEB;
        load_frags(base, 0u, Fr[0]);
        if (kt + NST - 1 < nk) issue_stage(kt + NST - 1);
        CP_COMMIT();
        #pragma unroll
        for (int ks = 0; ks < 4; ks++) {
            if (ks < 3)
                load_frags(base, (uint32_t)(ks + 1) * 32u, Fr[(ks + 1) & 1]);
            mma_step(Fr[ks & 1]);
        }
    }

    // fp32 split-K partial epilogue
    const int g  = lane >> 2;
    const int tg = lane & 3;
    float* base2 = Cpart + (size_t)blockIdx.z * ((size_t)M * N);
    #pragma unroll
    for (int mf = 0; mf < 2; mf++) {
        const int r0 = bm + warpm * 32 + mf * 16 + g;
        #pragma unroll
        for (int nf = 0; nf < 8; nf++) {
            const int col = bn + warpn * 64 + nf * 8 + tg * 2;
            *(float2*)(base2 + (size_t)r0 * N + col) =
                make_float2(acc[mf][nf][0], acc[mf][nf][1]);
            *(float2*)(base2 + (size_t)(r0 + 8) * N + col) =
                make_float2(acc[mf][nf][2], acc[mf][nf][3]);
        }
    }
}

// ---------------------------------------------------------------------------
// Pure fp16 activation GEMM: 128x128 tile, 1 MMA per product, 2 CTAs/SM.
// C[m][n] = sum_k A[m][k]*B[n][k]; fp32 accumulate.
// Warp grid 4m x 2n, warp tile 32x64 (16 independent accumulators/k16-step).
// ---------------------------------------------------------------------------
__global__ __launch_bounds__(256, 2)
void gemm_f16(const __half* __restrict__ Ap,
              const __half* __restrict__ Bp,
              const float* __restrict__ bias,
              __half* __restrict__ Cs,
              float* __restrict__ Cf,
              int M, int N, int K, int do_relu)
{
    extern __shared__ __align__(1024) char smem[];
    const uint32_t sb = (uint32_t)__cvta_generic_to_shared(smem);

    const int tid   = threadIdx.x;
    const int lane  = tid & 31;
    const int wid   = tid >> 5;
    const int warpm = wid & 3;
    const int warpn = wid >> 2;
    const int bm = blockIdx.y * 128;
    const int bn = blockIdx.x * 128;

    const uint32_t aOff = (uint32_t)(warpm * 32 + (lane & 15)) * ROWB
                        + (uint32_t)(lane >> 4) * 16u;
    const uint32_t bOff = (uint32_t)(warpn * 64 + (lane & 7) + ((lane & 16) ? 8 : 0)) * ROWB
                        + (uint32_t)((lane >> 3) & 1) * 16u;

    float acc[2][8][4];
    #pragma unroll
    for (int i = 0; i < 2; i++)
        #pragma unroll
        for (int j = 0; j < 8; j++)
            #pragma unroll
            for (int q = 0; q < 4; q++) acc[i][j][q] = 0.0f;

    const int nk = K >> 6;

    // 2048 16B chunks per stage (A 1024, B 1024) -> 8 cp.async per thread
    auto issue_stage = [&](int kt) {
        const uint32_t base = sb + (uint32_t)(kt % NST2) * STAGEB2;
        const size_t kof = (size_t)kt * BK;
        #pragma unroll
        for (int h = 0; h < 4; h++) {
            const int c   = tid + h * 256;
            const int row = c >> 3;
            const int q   = c & 7;
            const uint32_t so = (uint32_t)row * ROWB + (uint32_t)q * 16u;
            CP16(base + so,         Ap + (size_t)(bm + row) * K + kof + (size_t)q * 8);
            CP16(base + TILEB + so, Bp + (size_t)(bn + row) * K + kof + (size_t)q * 8);
        }
    };

    // F[0..7]=A(mf0,mf1), F[8..23]=B(bf0..bf3)
    auto load_frags = [&](uint32_t base, uint32_t kb, uint32_t* F) {
        const uint32_t bT = base + TILEB;
        #pragma unroll
        for (int mf = 0; mf < 2; mf++) {
            uint32_t ad = base + aOff + (uint32_t)mf * (16u * ROWB) + kb;
            LDSM4(F[mf*4+0], F[mf*4+1], F[mf*4+2], F[mf*4+3], ad);
        }
        #pragma unroll
        for (int bf = 0; bf < 4; bf++) {
            uint32_t bd = bT + bOff + (uint32_t)bf * (16u * ROWB) + kb;
            LDSM4(F[8+bf*4+0], F[8+bf*4+1], F[8+bf*4+2], F[8+bf*4+3], bd);
        }
    };

    auto mma_step = [&](const uint32_t* F) {
        #pragma unroll
        for (int mf = 0; mf < 2; mf++)
            #pragma unroll
            for (int nf = 0; nf < 8; nf++) {
                const uint32_t* BF = &F[8 + (nf >> 1) * 4];
                uint32_t bb[2] = { BF[(nf & 1) ? 2 : 0], BF[(nf & 1) ? 3 : 1] };
                MMA_F16(acc[mf][nf], &F[mf * 4], bb);
            }
    };

    #pragma unroll
    for (int s = 0; s < NST2 - 1; s++) { issue_stage(s); CP_COMMIT(); }

    uint32_t F[24];

    for (int kt = 0; kt < nk; kt++) {
        CP_WAIT(NST2 - 2);
        __syncthreads();
        const uint32_t base = sb + (uint32_t)(kt % NST2) * STAGEB2;
        if (kt + NST2 - 1 < nk) issue_stage(kt + NST2 - 1);
        CP_COMMIT();
        #pragma unroll
        for (int ks = 0; ks < 4; ks++) {
            load_frags(base, (uint32_t)ks * 32u, F);
            mma_step(F);
        }
    }

    // ---- epilogue ----
    const int g  = lane >> 2;
    const int tg = lane & 3;
    #pragma unroll
    for (int mf = 0; mf < 2; mf++) {
        const int r0 = bm + warpm * 32 + mf * 16 + g;
        #pragma unroll
        for (int nf = 0; nf < 8; nf++) {
            const int col = bn + warpn * 64 + nf * 8 + tg * 2;
            float b0 = bias[col], b1 = bias[col + 1];
            float v0 = acc[mf][nf][0] + b0, v1 = acc[mf][nf][1] + b1;
            float v2 = acc[mf][nf][2] + b0, v3 = acc[mf][nf][3] + b1;
            if (do_relu) {
                v0 = fmaxf(v0, 0.0f); v1 = fmaxf(v1, 0.0f);
                v2 = fmaxf(v2, 0.0f); v3 = fmaxf(v3, 0.0f);
            }
            if (Cf) {      // final: N==512; cols [0,256) mu, [256,512) logvar
                float* p0;
                float* p1;
                if (col < 256) {
                    p0 = Cf + (size_t)r0 * 256 + col;
                    p1 = Cf + (size_t)(r0 + 8) * 256 + col;
                } else {
                    float* half2p = Cf + (size_t)BATCH * 256;
                    p0 = half2p + (size_t)r0 * 256 + (col - 256);
                    p1 = half2p + (size_t)(r0 + 8) * 256 + (col - 256);
                }
                *(float2*)p0 = make_float2(v0, v1);
                *(float2*)p1 = make_float2(v2, v3);
            } else {
                *(uint32_t*)(Cs + (size_t)r0 * N + col)       = packh(v0, v1);
                *(uint32_t*)(Cs + (size_t)(r0 + 8) * N + col) = packh(v2, v3);
            }
        }
    }
}

// ---------------------------------------------------------------------------
// Launch
// ---------------------------------------------------------------------------
extern "C" void kernel_launch(void* const* d_in, const int* in_sizes, int n_in,
                              void* d_out, int out_size)
{
    const float* x   = (const float*)d_in[0];
    const float* fw  = (const float*)d_in[1];
    const float* kp  = (const float*)d_in[2];
    const float* W1  = (const float*)d_in[3];
    const float* b1  = (const float*)d_in[4];
    const float* W2  = (const float*)d_in[5];
    const float* b2  = (const float*)d_in[6];
    const float* Wmu = (const float*)d_in[7];
    const float* bmu = (const float*)d_in[8];
    const float* Wlv = (const float*)d_in[9];
    const float* blv = (const float*)d_in[10];
    float* out = (float*)d_out;

    __nv_bfloat16 *Dt_h, *Dt_l, *Dm_h, *Dm_l, *W1_h, *W1_l, *A1_h, *A1_l;
    __half *x16, *h1_16, *h2_16, *W1ef, *W2f, *Wmlf;
    float *bml, *bscale, *part;
    cudaGetSymbolAddress((void**)&Dt_h,  g_Dt_hi);  cudaGetSymbolAddress((void**)&Dt_l, g_Dt_lo);
    cudaGetSymbolAddress((void**)&Dm_h,  g_Dm_hi);  cudaGetSymbolAddress((void**)&Dm_l, g_Dm_lo);
    cudaGetSymbolAddress((void**)&W1_h,  g_W1_hi);  cudaGetSymbolAddress((void**)&W1_l, g_W1_lo);
    cudaGetSymbolAddress((void**)&A1_h,  g_A1_hi);  cudaGetSymbolAddress((void**)&A1_l, g_A1_lo);
    cudaGetSymbolAddress((void**)&x16,   g_x16);
    cudaGetSymbolAddress((void**)&h1_16, g_h1_16);
    cudaGetSymbolAddress((void**)&h2_16, g_h2_16);
    cudaGetSymbolAddress((void**)&W1ef,  g_W1ef);
    cudaGetSymbolAddress((void**)&W2f,   g_W2f);
    cudaGetSymbolAddress((void**)&Wmlf,  g_Wmlf);
    cudaGetSymbolAddress((void**)&bml,   g_bml);
    cudaGetSymbolAddress((void**)&bscale, g_bscale);
    cudaGetSymbolAddress((void**)&part,  g_part);

    cudaFuncSetAttribute(gemm_bf16x3,
                         cudaFuncAttributeMaxDynamicSharedMemorySize, SMEM_GEMM);
    cudaFuncSetAttribute(gemm_f16,
                         cudaFuncAttributeMaxDynamicSharedMemorySize, SMEM_GEMM2);

    build_scale_kernel<<<8, 256>>>(fw, kp);
    build_D_kernel<<<(DIMN * DIMN) / 256, 256>>>();

    convert_f16<<<(BATCH * DIMN / 8 + 255) / 256, 256>>>(x, x16, BATCH * DIMN);
    convert_split<<<(1024 * DIMN / 8 + 255) / 256, 256>>>(W1, W1_h, W1_l, 1024 * DIMN);
    convert_f16<<<(512 * 1024 / 8 + 255) / 256, 256>>>(W2, W2f, 512 * 1024);
    convert_f16<<<(256 * 512 / 8 + 255) / 256, 256>>>(Wmu, Wmlf, 256 * 512);
    convert_f16<<<(256 * 512 / 8 + 255) / 256, 256>>>(Wlv, Wmlf + 256 * 512, 256 * 512);
    merge_bias<<<2, 256>>>(bmu, blv);

    const int nW = 1024 * DIMN;

    // A1[j][kf] = (sum_n W1[j][n] * D[kf][n]) * bscale[kf]   (split-K=4, bf16x3)
    gemm_bf16x3<<<dim3(16, 8, 4), 256, SMEM_GEMM>>>(
        W1_h, W1_l, Dm_h, Dm_l, part, 1024, 2048, 2048, 512);
    reduce4_split<<<(nW / 4 + 255) / 256, 256>>>(part, bscale, A1_h, A1_l, nW, 2048);

    // W1e[j][m] = sum_kf A1[j][kf] * Dt[m][kf]               (split-K=4, bf16x3)
    gemm_bf16x3<<<dim3(16, 8, 4), 256, SMEM_GEMM>>>(
        A1_h, A1_l, Dt_h, Dt_l, part, 1024, 2048, 2048, 512);
    reduce4_f16<<<(nW / 4 + 255) / 256, 256>>>(part, W1ef, nW);

    // h1 = relu(x @ W1e^T + b1)        (pure fp16, 1 MMA/product)
    gemm_f16<<<dim3(8, 128), 256, SMEM_GEMM2>>>(
        x16, W1ef, b1, h1_16, nullptr, BATCH, 1024, 2048, 1);
    // h2 = relu(h1 @ W2^T + b2)
    gemm_f16<<<dim3(4, 128), 256, SMEM_GEMM2>>>(
        h1_16, W2f, b2, h2_16, nullptr, BATCH, 512, 1024, 1);
    // [mu | logvar] = h2 @ [Wmu;Wlv]^T + [bmu;blv]
    gemm_f16<<<dim3(4, 128), 256, SMEM_GEMM2>>>(
        h2_16, Wmlf, bml, nullptr, out, BATCH, 512, 512, 0);
}

// round 12
// speedup vs baseline: 2.4779x; 1.2391x over previous
#include <cuda_runtime.h>
#include <cuda_fp16.h>
#include <math.h>
#include <stdint.h>

// Problem constants
#define DIMN  2048
#define BATCH 16384

// Tile constants (verified R10-R11)
#define BK    64
#define ROWB  144u                    // 128B data + 16B pad -> conflict-free LDSM
#define TILEB (128u * ROWB)           // 18432 B per 128x64 fp16 tile
#define NST   3
#define STAGEB (2u * TILEB)           // A + B single tiles = 36864
#define SMEM_GEMM (NST * STAGEB)      // 110592 B -> 2 CTAs/SM

// ---------------------------------------------------------------------------
// Device scratch (static — no runtime allocs)
// ---------------------------------------------------------------------------
__device__ __align__(128) __half g_Dt   [DIMN * DIMN];   // Dt[m][k] = D[k][m]
__device__ __align__(128) __half g_Dm   [DIMN * DIMN];   // Dm[k][n] = D[k][n]
__device__ __align__(128) __half g_W1f  [1024 * DIMN];
__device__ __align__(128) __half g_A1f  [1024 * DIMN];
__device__ __align__(128) __half g_W1ef [1024 * DIMN];
__device__ __align__(128) __half g_x16  [BATCH * DIMN];
__device__ __align__(128) __half g_h1_16[BATCH * 1024];
__device__ __align__(128) __half g_h2_16[BATCH * 512];
__device__ __align__(128) __half g_W2f  [512 * 1024];
__device__ __align__(128) __half g_Wmlf [512 * 512];
__device__ __align__(128) float g_part[4 * 1024 * DIMN]; // split-K partials
__device__ float g_bml[512];
__device__ float g_bscale[DIMN];

// ---------------------------------------------------------------------------
// Band-scale (verified round 1)
// ---------------------------------------------------------------------------
__global__ void build_scale_kernel(const float* __restrict__ fw,
                                   const float* __restrict__ kptr)
{
    int idx = blockIdx.x * blockDim.x + threadIdx.x;
    if (idx >= DIMN) return;
    const float kv = *kptr;
    float val = 1.0f;
    const double step = 2047.0 / 30.0;
    #pragma unroll 1
    for (int i = 0; i < 30; i++) {
        int s = (int)(step * (double)i);
        int e = (i == 29) ? 2047 : (int)(step * (double)(i + 1));
        if (idx >= s && idx < e) {
            float f;
            if (e <= 30) f = 1.0f + fw[i] * kv * (1.0f - (float)i / 30.0f);
            else         f = 1.0f - fw[i] * kv * (1.0f - (float)(i - 30) / 30.0f);
            val = f;
        }
    }
    g_bscale[idx] = val;
}

static __device__ __forceinline__ uint32_t packh(float a, float b)
{
    __half2 t = __floats2half2_rn(a, b);
    return *reinterpret_cast<uint32_t*>(&t);
}

// ---------------------------------------------------------------------------
// Build Dt (D^T) and Dm (D) as fp16 (exact integer angle reduction + cospif)
// ---------------------------------------------------------------------------
__global__ void build_D_kernel()
{
    int idx = blockIdx.x * blockDim.x + threadIdx.x;
    int r = idx >> 11;
    int c = idx & (DIMN - 1);
    const float n0 = 0.022097086912079612f;  // sqrt(1/2048)
    const float n1 = 0.03125f;               // sqrt(2/2048)

    int q1 = ((2 * r + 1) * c) & 8191;
    float v1 = cospif((float)q1 * (1.0f / 4096.0f)) * ((c == 0) ? n0 : n1);
    g_Dt[idx] = __float2half_rn(v1);

    int q2 = ((2 * c + 1) * r) & 8191;
    float v2 = cospif((float)q2 * (1.0f / 4096.0f)) * ((r == 0) ? n0 : n1);
    g_Dm[idx] = __float2half_rn(v2);
}

// ---------------------------------------------------------------------------
// fp32 -> fp16 convert, 8 elems/thread (verified R9-R11)
// ---------------------------------------------------------------------------
__global__ void convert_f16(const float* __restrict__ s,
                            __half* __restrict__ d, int n)
{
    int i = (blockIdx.x * blockDim.x + threadIdx.x) << 3;
    if (i >= n) return;
    float4 v0 = *(const float4*)(s + i);
    float4 v1 = *(const float4*)(s + i + 4);
    uint4 buf;
    buf.x = packh(v0.x, v0.y); buf.y = packh(v0.z, v0.w);
    buf.z = packh(v1.x, v1.y); buf.w = packh(v1.z, v1.w);
    *(uint4*)(d + i) = buf;
}

// sum 4 split-K fp32 partials -> (optional colscale) -> single fp16
// N must be a power of two.
__global__ void reduce4_f16(const float* __restrict__ part,
                            const float* __restrict__ colscale,
                            __half* __restrict__ dst, int n, int N)
{
    int i = (blockIdx.x * blockDim.x + threadIdx.x) << 2;
    if (i >= n) return;
    float4 a = *(const float4*)(part + i);
    float4 b = *(const float4*)(part + (size_t)n + i);
    float4 c = *(const float4*)(part + 2 * (size_t)n + i);
    float4 d = *(const float4*)(part + 3 * (size_t)n + i);
    float v0 = (a.x + b.x) + (c.x + d.x);
    float v1 = (a.y + b.y) + (c.y + d.y);
    float v2 = (a.z + b.z) + (c.z + d.z);
    float v3 = (a.w + b.w) + (c.w + d.w);
    if (colscale) {
        int col = i & (N - 1);
        v0 *= colscale[col];     v1 *= colscale[col + 1];
        v2 *= colscale[col + 2]; v3 *= colscale[col + 3];
    }
    uint2 buf;
    buf.x = packh(v0, v1);
    buf.y = packh(v2, v3);
    *(uint2*)(dst + i) = buf;
}

__global__ void merge_bias(const float* __restrict__ bmu, const float* __restrict__ blv)
{
    int i = blockIdx.x * blockDim.x + threadIdx.x;
    if (i < 256)      g_bml[i] = bmu[i];
    else if (i < 512) g_bml[i] = blv[i - 256];
}

// ---------------------------------------------------------------------------
// mma.sync / ldmatrix / cp.async helpers
// ---------------------------------------------------------------------------
#define LDSM4(r0, r1, r2, r3, addr)                                            \
    asm volatile("ldmatrix.sync.aligned.m8n8.x4.shared.b16 {%0,%1,%2,%3}, [%4];" \
                 : "=r"(r0), "=r"(r1), "=r"(r2), "=r"(r3) : "r"(addr))

#define MMA_F16(c, a, b)                                                       \
    asm volatile("mma.sync.aligned.m16n8k16.row.col.f32.f16.f16.f32 "          \
                 "{%0,%1,%2,%3},{%4,%5,%6,%7},{%8,%9},{%0,%1,%2,%3};"          \
                 : "+f"((c)[0]), "+f"((c)[1]), "+f"((c)[2]), "+f"((c)[3])      \
                 : "r"((a)[0]), "r"((a)[1]), "r"((a)[2]), "r"((a)[3]),         \
                   "r"((b)[0]), "r"((b)[1]))

#define CP16(sa, ga)                                                           \
    asm volatile("cp.async.cg.shared.global [%0], [%1], 16;"                   \
                 :: "r"(sa), "l"(ga) : "memory")
#define CP_COMMIT() asm volatile("cp.async.commit_group;" ::: "memory")
#define CP_WAIT()   asm volatile("cp.async.wait_group %0;" :: "n"(NST - 2) : "memory")

// ---------------------------------------------------------------------------
// Pure fp16 NT GEMM (verified R11), now with split-K Cpart mode.
// C[m][n] = sum_{k in [kbase, kbase+klen)} A[m][k]*B[n][k]; fp32 accumulate.
// 128x128 CTA tile, warp grid 4m x 2n (warp tile 32x64), 3 stages, 2 CTA/SM.
// Output: Cpart (fp32 split-K plane) | Cf (fp32 final mu/logvar) | Cs (fp16).
// ---------------------------------------------------------------------------
__global__ __launch_bounds__(256, 2)
void gemm_f16(const __half* __restrict__ Ap,
              const __half* __restrict__ Bp,
              const float* __restrict__ bias,
              __half* __restrict__ Cs,
              float* __restrict__ Cf,
              float* __restrict__ Cpart,
              int M, int N, int K, int klen, int do_relu)
{
    extern __shared__ __align__(1024) char smem[];
    const uint32_t sb = (uint32_t)__cvta_generic_to_shared(smem);

    const int tid   = threadIdx.x;
    const int lane  = tid & 31;
    const int wid   = tid >> 5;
    const int warpm = wid & 3;
    const int warpn = wid >> 2;
    const int bm = blockIdx.y * 128;
    const int bn = blockIdx.x * 128;
    const int kbase = blockIdx.z * klen;

    const uint32_t aOff = (uint32_t)(warpm * 32 + (lane & 15)) * ROWB
                        + (uint32_t)(lane >> 4) * 16u;
    const uint32_t bOff = (uint32_t)(warpn * 64 + (lane & 7) + ((lane & 16) ? 8 : 0)) * ROWB
                        + (uint32_t)((lane >> 3) & 1) * 16u;

    float acc[2][8][4];
    #pragma unroll
    for (int i = 0; i < 2; i++)
        #pragma unroll
        for (int j = 0; j < 8; j++)
            #pragma unroll
            for (int q = 0; q < 4; q++) acc[i][j][q] = 0.0f;

    const int nk = klen >> 6;

    auto issue_stage = [&](int kt) {
        const uint32_t base = sb + (uint32_t)(kt % NST) * STAGEB;
        const size_t kof = (size_t)kbase + (size_t)kt * BK;
        #pragma unroll
        for (int h = 0; h < 4; h++) {
            const int c   = tid + h * 256;
            const int row = c >> 3;
            const int q   = c & 7;
            const uint32_t so = (uint32_t)row * ROWB + (uint32_t)q * 16u;
            CP16(base + so,         Ap + (size_t)(bm + row) * K + kof + (size_t)q * 8);
            CP16(base + TILEB + so, Bp + (size_t)(bn + row) * K + kof + (size_t)q * 8);
        }
    };

    // F[0..7]=A(mf0,mf1), F[8..23]=B(bf0..bf3)
    auto load_frags = [&](uint32_t base, uint32_t kb, uint32_t* F) {
        const uint32_t bT = base + TILEB;
        #pragma unroll
        for (int mf = 0; mf < 2; mf++) {
            uint32_t ad = base + aOff + (uint32_t)mf * (16u * ROWB) + kb;
            LDSM4(F[mf*4+0], F[mf*4+1], F[mf*4+2], F[mf*4+3], ad);
        }
        #pragma unroll
        for (int bf = 0; bf < 4; bf++) {
            uint32_t bd = bT + bOff + (uint32_t)bf * (16u * ROWB) + kb;
            LDSM4(F[8+bf*4+0], F[8+bf*4+1], F[8+bf*4+2], F[8+bf*4+3], bd);
        }
    };

    auto mma_step = [&](const uint32_t* F) {
        #pragma unroll
        for (int mf = 0; mf < 2; mf++)
            #pragma unroll
            for (int nf = 0; nf < 8; nf++) {
                const uint32_t* BF = &F[8 + (nf >> 1) * 4];
                uint32_t bb[2] = { BF[(nf & 1) ? 2 : 0], BF[(nf & 1) ? 3 : 1] };
                MMA_F16(acc[mf][nf], &F[mf * 4], bb);
            }
    };

    #pragma unroll
    for (int s = 0; s < NST - 1; s++) { issue_stage(s); CP_COMMIT(); }

    uint32_t F[24];

    for (int kt = 0; kt < nk; kt++) {
        CP_WAIT();
        __syncthreads();
        const uint32_t base = sb + (uint32_t)(kt % NST) * STAGEB;
        if (kt + NST - 1 < nk) issue_stage(kt + NST - 1);
        CP_COMMIT();
        #pragma unroll
        for (int ks = 0; ks < 4; ks++) {
            load_frags(base, (uint32_t)ks * 32u, F);
            mma_step(F);
        }
    }

    // ---- epilogue ----
    const int g  = lane >> 2;
    const int tg = lane & 3;
    #pragma unroll
    for (int mf = 0; mf < 2; mf++) {
        const int r0 = bm + warpm * 32 + mf * 16 + g;
        #pragma unroll
        for (int nf = 0; nf < 8; nf++) {
            const int col = bn + warpn * 64 + nf * 8 + tg * 2;
            float v0 = acc[mf][nf][0], v1 = acc[mf][nf][1];
            float v2 = acc[mf][nf][2], v3 = acc[mf][nf][3];

            if (Cpart) {   // split-K fp32 partial, plane = blockIdx.z
                float* base2 = Cpart + (size_t)blockIdx.z * ((size_t)M * N);
                *(float2*)(base2 + (size_t)r0 * N + col)       = make_float2(v0, v1);
                *(float2*)(base2 + (size_t)(r0 + 8) * N + col) = make_float2(v2, v3);
                continue;
            }
            float b0 = bias[col], b1 = bias[col + 1];
            v0 += b0; v1 += b1; v2 += b0; v3 += b1;
            if (do_relu) {
                v0 = fmaxf(v0, 0.0f); v1 = fmaxf(v1, 0.0f);
                v2 = fmaxf(v2, 0.0f); v3 = fmaxf(v3, 0.0f);
            }
            if (Cf) {      // final: N==512; cols [0,256) mu, [256,512) logvar
                float* p0;
                float* p1;
                if (col < 256) {
                    p0 = Cf + (size_t)r0 * 256 + col;
                    p1 = Cf + (size_t)(r0 + 8) * 256 + col;
                } else {
                    float* half2p = Cf + (size_t)BATCH * 256;
                    p0 = half2p + (size_t)r0 * 256 + (col - 256);
                    p1 = half2p + (size_t)(r0 + 8) * 256 + (col - 256);
                }
                *(float2*)p0 = make_float2(v0, v1);
                *(float2*)p1 = make_float2(v2, v3);
            } else {
                *(uint32_t*)(Cs + (size_t)r0 * N + col)       = packh(v0, v1);
                *(uint32_t*)(Cs + (size_t)(r0 + 8) * N + col) = packh(v2, v3);
            }
        }
    }
}

// ---------------------------------------------------------------------------
// Launch: all-fp16 pipeline.
//   A1  = (W1 @ D^T_rows) * diag(bscale)   [split-K=4]
//   W1e = A1 @ Dt                          [split-K=4]
//   h1  = relu(x @ W1e^T + b1); h2 = relu(h1 @ W2^T + b2); out = h2 @ Wml^T
// ---------------------------------------------------------------------------
extern "C" void kernel_launch(void* const* d_in, const int* in_sizes, int n_in,
                              void* d_out, int out_size)
{
    const float* x   = (const float*)d_in[0];
    const float* fw  = (const float*)d_in[1];
    const float* kp  = (const float*)d_in[2];
    const float* W1  = (const float*)d_in[3];
    const float* b1  = (const float*)d_in[4];
    const float* W2  = (const float*)d_in[5];
    const float* b2  = (const float*)d_in[6];
    const float* Wmu = (const float*)d_in[7];
    const float* bmu = (const float*)d_in[8];
    const float* Wlv = (const float*)d_in[9];
    const float* blv = (const float*)d_in[10];
    float* out = (float*)d_out;

    __half *Dt, *Dm, *W1f, *A1f, *W1ef, *x16, *h1_16, *h2_16, *W2f, *Wmlf;
    float *bml, *bscale, *part;
    cudaGetSymbolAddress((void**)&Dt,    g_Dt);
    cudaGetSymbolAddress((void**)&Dm,    g_Dm);
    cudaGetSymbolAddress((void**)&W1f,   g_W1f);
    cudaGetSymbolAddress((void**)&A1f,   g_A1f);
    cudaGetSymbolAddress((void**)&W1ef,  g_W1ef);
    cudaGetSymbolAddress((void**)&x16,   g_x16);
    cudaGetSymbolAddress((void**)&h1_16, g_h1_16);
    cudaGetSymbolAddress((void**)&h2_16, g_h2_16);
    cudaGetSymbolAddress((void**)&W2f,   g_W2f);
    cudaGetSymbolAddress((void**)&Wmlf,  g_Wmlf);
    cudaGetSymbolAddress((void**)&bml,   g_bml);
    cudaGetSymbolAddress((void**)&bscale, g_bscale);
    cudaGetSymbolAddress((void**)&part,  g_part);

    cudaFuncSetAttribute(gemm_f16,
                         cudaFuncAttributeMaxDynamicSharedMemorySize, SMEM_GEMM);

    build_scale_kernel<<<8, 256>>>(fw, kp);
    build_D_kernel<<<(DIMN * DIMN) / 256, 256>>>();

    convert_f16<<<(BATCH * DIMN / 8 + 255) / 256, 256>>>(x, x16, BATCH * DIMN);
    convert_f16<<<(1024 * DIMN / 8 + 255) / 256, 256>>>(W1, W1f, 1024 * DIMN);
    convert_f16<<<(512 * 1024 / 8 + 255) / 256, 256>>>(W2, W2f, 512 * 1024);
    convert_f16<<<(256 * 512 / 8 + 255) / 256, 256>>>(Wmu, Wmlf, 256 * 512);
    convert_f16<<<(256 * 512 / 8 + 255) / 256, 256>>>(Wlv, Wmlf + 256 * 512, 256 * 512);
    merge_bias<<<2, 256>>>(bmu, blv);

    const int nW = 1024 * DIMN;

    // A1[j][kf] = (sum_n W1[j][n] * D[kf][n]) * bscale[kf]   (split-K=4)
    gemm_f16<<<dim3(16, 8, 4), 256, SMEM_GEMM>>>(
        W1f, Dm, nullptr, nullptr, nullptr, part, 1024, 2048, 2048, 512, 0);
    reduce4_f16<<<(nW / 4 + 255) / 256, 256>>>(part, bscale, A1f, nW, 2048);

    // W1e[j][m] = sum_kf A1[j][kf] * Dt[m][kf]               (split-K=4)
    gemm_f16<<<dim3(16, 8, 4), 256, SMEM_GEMM>>>(
        A1f, Dt, nullptr, nullptr, nullptr, part, 1024, 2048, 2048, 512, 0);
    reduce4_f16<<<(nW / 4 + 255) / 256, 256>>>(part, nullptr, W1ef, nW, 2048);

    // h1 = relu(x @ W1e^T + b1)
    gemm_f16<<<dim3(8, 128, 1), 256, SMEM_GEMM>>>(
        x16, W1ef, b1, h1_16, nullptr, nullptr, BATCH, 1024, 2048, 2048, 1);
    // h2 = relu(h1 @ W2^T + b2)
    gemm_f16<<<dim3(4, 128, 1), 256, SMEM_GEMM>>>(
        h1_16, W2f, b2, h2_16, nullptr, nullptr, BATCH, 512, 1024, 1024, 1);
    // [mu | logvar] = h2 @ [Wmu;Wlv]^T + [bmu;blv]
    gemm_f16<<<dim3(4, 128, 1), 256, SMEM_GEMM>>>(
        h2_16, Wmlf, bml, nullptr, out, nullptr, BATCH, 512, 512, 512, 0);
}